// round 10
// baseline (speedup 1.0000x reference)
#include <cuda_runtime.h>
#include <cuda_fp16.h>
#include <cstdint>
#include <cstddef>

#define DIM   64
#define CBK   4096
#define MAXM  32768
#define KU    128            // rescore slices [h1|h2]
#define BM    128
#define TAU   0.15f
#define CAP   16384

// ---------------------------------------------------------------------------
// Device scratch (static)
// ---------------------------------------------------------------------------
__device__ float g_nhn[CBK];                                   // -0.5*||e||^2
__device__ __align__(256) __half g_es[(size_t)CBK * KU];       // e: h1|h2 (rescore)
__device__ __align__(256) uint4 g_e1f4[32768];                 // e1 frags, j-paired
__device__ int g_cnt;
__device__ int g_done[CAP / BM];
__device__ int g_flag[CAP];
__device__ unsigned long long g_best[CAP];

// ---------------------------------------------------------------------------
// PTX helpers
// ---------------------------------------------------------------------------
__device__ __forceinline__ uint32_t smem_u32(const void* p) {
    uint32_t a;
    asm("{ .reg .u64 t; cvta.to.shared.u64 t, %1; cvt.u32.u64 %0, t; }"
        : "=r"(a) : "l"(p));
    return a;
}
__device__ __forceinline__ void cp16(uint32_t dst, const void* src) {
    asm volatile("cp.async.cg.shared.global [%0], [%1], 16;" :: "r"(dst), "l"(src));
}
__device__ __forceinline__ void cp_commit() {
    asm volatile("cp.async.commit_group;");
}
#define CP_WAIT(n) asm volatile("cp.async.wait_group %0;" :: "n"(n) : "memory")
__device__ __forceinline__ void ldsm4(uint32_t* r, uint32_t addr) {
    asm volatile("ldmatrix.sync.aligned.m8n8.x4.shared.b16 {%0,%1,%2,%3}, [%4];"
                 : "=r"(r[0]), "=r"(r[1]), "=r"(r[2]), "=r"(r[3]) : "r"(addr));
}
__device__ __forceinline__ void ldsm2(uint32_t* r, uint32_t addr) {
    asm volatile("ldmatrix.sync.aligned.m8n8.x2.shared.b16 {%0,%1}, [%2];"
                 : "=r"(r[0]), "=r"(r[1]) : "r"(addr));
}
__device__ __forceinline__ void hmma(float* d, const uint32_t* a, const uint32_t* b) {
    asm volatile("mma.sync.aligned.m16n8k16.row.col.f32.f16.f16.f32 "
                 "{%0,%1,%2,%3}, {%4,%5,%6,%7}, {%8,%9}, {%0,%1,%2,%3};"
                 : "+f"(d[0]), "+f"(d[1]), "+f"(d[2]), "+f"(d[3])
                 : "r"(a[0]), "r"(a[1]), "r"(a[2]), "r"(a[3]),
                   "r"(b[0]), "r"(b[1]));
}
// D = A*B + {cx, cy, cx, cy}  (accumulator *init* — D != C form)
__device__ __forceinline__ void hmma_c(float* d, const uint32_t* a, const uint32_t* b,
                                       float cx, float cy) {
    asm volatile("mma.sync.aligned.m16n8k16.row.col.f32.f16.f16.f32 "
                 "{%0,%1,%2,%3}, {%4,%5,%6,%7}, {%8,%9}, {%10,%11,%10,%11};"
                 : "=f"(d[0]), "=f"(d[1]), "=f"(d[2]), "=f"(d[3])
                 : "r"(a[0]), "r"(a[1]), "r"(a[2]), "r"(a[3]),
                   "r"(b[0]), "r"(b[1]), "f"(cx), "f"(cy));
}
__device__ __forceinline__ uint32_t fkey(float f) {
    uint32_t u = __float_as_uint(f);
    return (u & 0x80000000u) ? ~u : (u | 0x80000000u);
}

// ---------------------------------------------------------------------------
// Split fp32 -> (h1,h2) fp16.  Exact 3-term score: h1e1 + h1e2 + h2e1.
// ---------------------------------------------------------------------------
__device__ __forceinline__ void split8(float4 lo, float4 hi, uint4* h) {
    float v[8] = {lo.x, lo.y, lo.z, lo.w, hi.x, hi.y, hi.z, hi.w};
    union U { unsigned short s[8]; uint4 u; } u1, u2;
#pragma unroll
    for (int k = 0; k < 8; k++) {
        float a = v[k];
        __half b1 = __float2half_rn(a);
        float r1 = a - __half2float(b1);
        __half b2 = __float2half_rn(r1);
        u1.s[k] = *reinterpret_cast<unsigned short*>(&b1);
        u2.s[k] = *reinterpret_cast<unsigned short*>(&b2);
    }
    h[0] = u1.u; h[1] = u2.u;
}

// h1-only conversion of 8 floats -> uint4 of halves
__device__ __forceinline__ uint4 cvt8(float4 lo, float4 hi) {
    uint4 v;
    __half2 a = __floats2half2_rn(lo.x, lo.y);
    __half2 b = __floats2half2_rn(lo.z, lo.w);
    __half2 c = __floats2half2_rn(hi.x, hi.y);
    __half2 d = __floats2half2_rn(hi.z, hi.w);
    v.x = *reinterpret_cast<uint32_t*>(&a);
    v.y = *reinterpret_cast<uint32_t*>(&b);
    v.z = *reinterpret_cast<uint32_t*>(&c);
    v.w = *reinterpret_cast<uint32_t*>(&d);
    return v;
}

// ---------------------------------------------------------------------------
// Prologue (e-side only): init state, split e (+ norms), pack e1 fragments.
// ---------------------------------------------------------------------------
__global__ void prep_kernel(const float* __restrict__ e) {
    const int gid = blockIdx.x * blockDim.x + threadIdx.x;

    if (gid == 0) g_cnt = 0;
    if (gid < CAP) g_best[gid] = 0ULL;
    if (gid < CAP / BM) g_done[gid] = 0;

    // ---- e split + norm (gid < CBK*8 = 32768) -----------------------------
    if (gid < CBK * 8) {
        int row = gid >> 3, c8 = gid & 7;
        const float4* p = reinterpret_cast<const float4*>(e + (size_t)row * DIM + c8 * 8);
        float4 lo = p[0], hi = p[1];
        uint4 h[2];
        split8(lo, hi, h);
        __half* dst = g_es + (size_t)row * KU + c8 * 8;
        *reinterpret_cast<uint4*>(dst)       = h[0];
        *reinterpret_cast<uint4*>(dst + DIM) = h[1];
        float s = lo.x * lo.x + lo.y * lo.y + lo.z * lo.z + lo.w * lo.w
                + hi.x * hi.x + hi.y * hi.y + hi.z * hi.z + hi.w * hi.w;
        s += __shfl_xor_sync(0xffffffffu, s, 1);
        s += __shfl_xor_sync(0xffffffffu, s, 2);
        s += __shfl_xor_sync(0xffffffffu, s, 4);
        if (c8 == 0) g_nhn[row] = -0.5f * s;
    }

    // ---- pack e1 fragments, j-paired uint4 (gid < 32768) -------------------
    if (gid < 32768) {
        int lane = gid & 31;
        int nf2  = (gid >> 5) & 7;
        int ks   = (gid >> 8) & 3;
        int nt   = gid >> 10;
        int k0 = ks * 16 + (lane & 3) * 2;
        uint4 v;
#pragma unroll
        for (int j = 0; j < 2; j++) {
            int n = nt * 128 + (nf2 * 2 + j) * 8 + (lane >> 2);
            const float* er = e + (size_t)n * DIM;
            __half2 b0 = __floats2half2_rn(er[k0], er[k0 + 1]);
            __half2 b1 = __floats2half2_rn(er[k0 + 8], er[k0 + 9]);
            if (j == 0) { v.x = *reinterpret_cast<uint32_t*>(&b0);
                          v.y = *reinterpret_cast<uint32_t*>(&b1); }
            else        { v.z = *reinterpret_cast<uint32_t*>(&b0);
                          v.w = *reinterpret_cast<uint32_t*>(&b1); }
        }
        g_e1f4[gid] = v;
    }
}

// ---------------------------------------------------------------------------
// Pass 1: single-term fp16 GEMM (h1 . e1) with nh folded into the MMA C
// operand; A built in-kernel from fp32 x; B via LDG.128 j-paired frags.
// Top-2 margin test; flagged row ids recorded for rescore.
// ---------------------------------------------------------------------------
#define P1_SMEM 16384

__global__ __launch_bounds__(256, 2)
void vq_pass1(const float* __restrict__ x,
              const float* __restrict__ embed,
              float* __restrict__ outq,
              float* __restrict__ out_ind) {
    extern __shared__ __align__(128) char smem[];
    const uint32_t As_u = smem_u32(smem);

    const int tid  = threadIdx.x;
    const int lane = tid & 31, wid = tid >> 5;
    const int wm = wid & 1, wn = wid >> 1;
    const int g = lane >> 2, tig = lane & 3;
    const int mtile = blockIdx.x;

    // ---- A tile: fp32 x -> h1 fp16, swizzled SMEM --------------------------
    {
        const float* xa = x + (size_t)mtile * BM * DIM;
#pragma unroll
        for (int i = 0; i < 4; i++) {
            int idx = tid + i * 256;          // 1024 16B fp16 chunks
            int row = idx >> 3, c = idx & 7;
            const float* src = xa + (size_t)row * DIM + c * 8;
            float4 lo = __ldg(reinterpret_cast<const float4*>(src));
            float4 hi = __ldg(reinterpret_cast<const float4*>(src + 4));
            *reinterpret_cast<uint4*>(smem + row * 128 + ((c ^ (row & 7)) << 4)) =
                cvt8(lo, hi);
        }
    }

    uint32_t aBase[4];
#pragma unroll
    for (int mi = 0; mi < 4; mi++)
        aBase[mi] = As_u + (wm * 64 + mi * 16 + (lane & 15)) * 128;
    const uint32_t amask = (lane & 7) << 4;
    const uint32_t asel  = lane >> 4;

    const uint4* bp4 = g_e1f4 + (size_t)(wn * 2) * 32 + lane;

    float b1[8], b2[8];
    int   i1[8];
#pragma unroll
    for (int s = 0; s < 8; s++) { b1[s] = -3.402823466e38f; b2[s] = -3.402823466e38f; i1[s] = 0; }

    __syncthreads();

    auto loadB = [&](int u, uint4 (&bf)[4]) {
        const int nt = u >> 1, h = u & 1;
        const uint4* p = bp4 + (size_t)nt * 1024 + h * 32;
#pragma unroll
        for (int ks = 0; ks < 4; ks++) bf[ks] = __ldg(p + ks * 256);
    };
    auto computeH = [&](int u, uint4 (&bf)[4]) {
        const int nt = u >> 1, h = u & 1;
        const int colb = nt * 128 + wn * 32 + h * 16 + tig * 2;
        const float2 nh0 = *reinterpret_cast<const float2*>(&g_nhn[colb]);
        const float2 nh1 = *reinterpret_cast<const float2*>(&g_nhn[colb + 8]);
        float acc[4][2][4];
        // ks = 0: accumulator initialized with nh via C operand
        {
            uint32_t a[4][4];
            const uint32_t aoff = ((uint32_t)asel << 4) ^ amask;
#pragma unroll
            for (int mi = 0; mi < 4; mi++) ldsm4(a[mi], aBase[mi] + aoff);
            const uint32_t* bw = reinterpret_cast<const uint32_t*>(&bf[0]);
#pragma unroll
            for (int mi = 0; mi < 4; mi++) {
                hmma_c(acc[mi][0], a[mi], bw,     nh0.x, nh0.y);
                hmma_c(acc[mi][1], a[mi], bw + 2, nh1.x, nh1.y);
            }
        }
#pragma unroll
        for (int ks = 1; ks < 4; ks++) {
            uint32_t a[4][4];
            const uint32_t aoff = (((uint32_t)(ks * 2) + asel) << 4) ^ amask;
#pragma unroll
            for (int mi = 0; mi < 4; mi++) ldsm4(a[mi], aBase[mi] + aoff);
            const uint32_t* bw = reinterpret_cast<const uint32_t*>(&bf[ks]);
#pragma unroll
            for (int mi = 0; mi < 4; mi++) {
                hmma(acc[mi][0], a[mi], bw);
                hmma(acc[mi][1], a[mi], bw + 2);
            }
        }
#pragma unroll
        for (int j = 0; j < 2; j++) {
            const int c0 = colb + j * 8;
#pragma unroll
            for (int mi = 0; mi < 4; mi++) {
                const int lo = mi * 2, hi = mi * 2 + 1;
                float s0 = acc[mi][j][0];
                float s1 = acc[mi][j][1];
                float s2 = acc[mi][j][2];
                float s3 = acc[mi][j][3];
                b2[lo] = fmaxf(b2[lo], fminf(b1[lo], s0));
                if (s0 > b1[lo]) { b1[lo] = s0; i1[lo] = c0; }
                b2[lo] = fmaxf(b2[lo], fminf(b1[lo], s1));
                if (s1 > b1[lo]) { b1[lo] = s1; i1[lo] = c0 + 1; }
                b2[hi] = fmaxf(b2[hi], fminf(b1[hi], s2));
                if (s2 > b1[hi]) { b1[hi] = s2; i1[hi] = c0; }
                b2[hi] = fmaxf(b2[hi], fminf(b1[hi], s3));
                if (s3 > b1[hi]) { b1[hi] = s3; i1[hi] = c0 + 1; }
            }
        }
    };

    uint4 bufA[4], bufB[4];
    loadB(0, bufA);
    for (int u = 0; u < 64; u += 2) {
        loadB(u + 1, bufB);
        computeH(u, bufA);
        if (u + 2 < 64) loadB(u + 2, bufA);
        computeH(u + 1, bufB);
    }

    // quad reduce (top-2 over disjoint candidate sets)
#pragma unroll
    for (int s = 0; s < 8; s++) {
#pragma unroll
        for (int d = 1; d < 4; d <<= 1) {
            float ov1 = __shfl_xor_sync(0xffffffffu, b1[s], d);
            int   oi1 = __shfl_xor_sync(0xffffffffu, i1[s], d);
            float ov2 = __shfl_xor_sync(0xffffffffu, b2[s], d);
            if (ov1 > b1[s] || (ov1 == b1[s] && oi1 < i1[s])) {
                b2[s] = fmaxf(b1[s], ov2); b1[s] = ov1; i1[s] = oi1;
            } else {
                b2[s] = fmaxf(b2[s], ov1);
            }
        }
    }
    __syncthreads();
    float* rv1 = reinterpret_cast<float*>(smem);
    int*   ri1 = reinterpret_cast<int*>(smem + 2048);
    float* rv2 = reinterpret_cast<float*>(smem + 4096);
    if (tig == 0) {
#pragma unroll
        for (int s = 0; s < 8; s++) {
            int row = wm * 64 + (s >> 1) * 16 + g + (s & 1) * 8;
            rv1[row * 4 + wn] = b1[s];
            ri1[row * 4 + wn] = i1[s];
            rv2[row * 4 + wn] = b2[s];
        }
    }
    __syncthreads();

    if (tid < BM) {
        float B1 = rv1[tid * 4], B2 = rv2[tid * 4];
        int   I1 = ri1[tid * 4];
#pragma unroll
        for (int j = 1; j < 4; j++) {
            float a1 = rv1[tid * 4 + j], a2 = rv2[tid * 4 + j];
            int   ai = ri1[tid * 4 + j];
            if (a1 > B1 || (a1 == B1 && ai < I1)) {
                B2 = fmaxf(B1, a2); B1 = a1; I1 = ai;
            } else {
                B2 = fmaxf(B2, a1);
            }
        }
        const int grow = mtile * BM + tid;
        if (out_ind) out_ind[grow] = (float)I1;
        const float4* e4 = reinterpret_cast<const float4*>(embed + (size_t)I1 * DIM);
        float4* o4 = reinterpret_cast<float4*>(outq + (size_t)grow * DIM);
#pragma unroll
        for (int i = 0; i < DIM / 4; i++) o4[i] = e4[i];
        if (B1 - B2 < TAU) {
            int pos = atomicAdd(&g_cnt, 1);
            if (pos < CAP) g_flag[pos] = grow;
        }
    }
}

// ---------------------------------------------------------------------------
// Rescore (exact 3-term) over flagged rows; A re-split from fp32 x inline.
// 8 codebook chunks x m-tiles; last-finishing chunk per tile writes back.
// ---------------------------------------------------------------------------
#define RS_SMEM (32768 + 65536)

template<int TERMS>
__device__ __forceinline__ void compute_stage(
    float (&acc)[4][4][4], const uint32_t* aBase, uint32_t amask, uint32_t asel,
    uint32_t bst, const uint32_t* bOff, uint32_t bmask, uint32_t bsel)
{
#pragma unroll
    for (int ks = 0; ks < 4; ks++) {
        uint32_t b[4][2];
        const uint32_t boff = (((uint32_t)(ks * 2) + bsel) << 4) ^ bmask;
#pragma unroll
        for (int ni = 0; ni < 4; ni++) ldsm2(b[ni], bst + bOff[ni] + boff);
        const uint32_t aoff = (((uint32_t)(ks * 2) + asel) << 4) ^ amask;
#pragma unroll
        for (int t = 0; t < TERMS; t++) {
            uint32_t a[4][4];
#pragma unroll
            for (int mi = 0; mi < 4; mi++)
                ldsm4(a[mi], aBase[mi] + t * 16384 + aoff);
#pragma unroll
            for (int mi = 0; mi < 4; mi++)
#pragma unroll
                for (int ni = 0; ni < 4; ni++)
                    hmma(acc[mi][ni], a[mi], b[ni]);
        }
    }
}

__global__ __launch_bounds__(256, 2)
void vq_rescore(const float* __restrict__ x,
                const float* __restrict__ embed,
                float* __restrict__ outq,
                float* __restrict__ out_ind) {
    int cnt = g_cnt; if (cnt > CAP) cnt = CAP;
    extern __shared__ __align__(128) char smem[];
    __shared__ int s_last;
    const uint32_t As_u = smem_u32(smem);
    const uint32_t Bs_u = As_u + 32768;

    const int tid  = threadIdx.x;
    const int lane = tid & 31, wid = tid >> 5;
    const int wm = wid & 1, wn = wid >> 1;
    const int g = lane >> 2, tig = lane & 3;
    const int nchunk = blockIdx.x;

    uint32_t aBase[4];
#pragma unroll
    for (int mi = 0; mi < 4; mi++)
        aBase[mi] = As_u + (wm * 64 + mi * 16 + (lane & 15)) * 128;
    const uint32_t amask = (lane & 7) << 4;
    const uint32_t asel  = lane >> 4;
    uint32_t bOff[4];
#pragma unroll
    for (int ni = 0; ni < 4; ni++)
        bOff[ni] = (wn * 32 + ni * 8 + (lane & 7)) * 128;
    const uint32_t bmask = (lane & 7) << 4;
    const uint32_t bsel  = (lane >> 3) & 1;

    auto prefetchB = [&](int st, int slot) {
        const int nt = nchunk * 4 + (st >> 1), s = st & 1;
        const __half* src = g_es + (size_t)nt * BM * KU + s * DIM;
        const uint32_t dbase = Bs_u + slot * 16384;
#pragma unroll
        for (int i = 0; i < 4; i++) {
            int idx = tid + i * 256;
            int row = idx >> 3, c = idx & 7;
            cp16(dbase + row * 128 + ((c ^ (row & 7)) << 4),
                 src + (size_t)row * KU + c * 8);
        }
    };

    for (int mt = blockIdx.y; mt * BM < cnt; mt += gridDim.y) {
        // A: flagged rows, split from fp32 x inline (h1 + h2 slices)
#pragma unroll
        for (int i = 0; i < 4; i++) {
            int idx = tid + i * 256;
            int row = idx >> 3, c = idx & 7;
            int ci = mt * BM + row; if (ci >= cnt) ci = cnt - 1;
            int grow = g_flag[ci];
            const float* src = x + (size_t)grow * DIM + c * 8;
            float4 lo = __ldg(reinterpret_cast<const float4*>(src));
            float4 hi = __ldg(reinterpret_cast<const float4*>(src + 4));
            uint4 h[2];
            split8(lo, hi, h);
            uint32_t off = row * 128 + ((c ^ (row & 7)) << 4);
            *reinterpret_cast<uint4*>(smem + off)         = h[0];
            *reinterpret_cast<uint4*>(smem + 16384 + off) = h[1];
        }
        prefetchB(0, 0); cp_commit();
        prefetchB(1, 1); cp_commit();
        prefetchB(2, 2); cp_commit();

        float bestv[8]; int bidxv[8];
#pragma unroll
        for (int s = 0; s < 8; s++) { bestv[s] = -3.402823466e38f; bidxv[s] = 0; }
        float acc[4][4][4];

        for (int si = 0; si < 8; si++) {
            const int cs = si & 1, ntl = si >> 1;
            CP_WAIT(2);
            __syncthreads();
            if (si < 5) prefetchB(si + 3, (si + 3) & 3);
            cp_commit();

            if (cs == 0) {
#pragma unroll
                for (int mi = 0; mi < 4; mi++)
#pragma unroll
                    for (int ni = 0; ni < 4; ni++)
#pragma unroll
                        for (int r = 0; r < 4; r++) acc[mi][ni][r] = 0.f;
            }
            const uint32_t bst = Bs_u + (si & 3) * 16384;
            if (cs == 0) compute_stage<2>(acc, aBase, amask, asel, bst, bOff, bmask, bsel);
            else         compute_stage<1>(acc, aBase, amask, asel, bst, bOff, bmask, bsel);

            if (cs == 1) {
                const int colb = (nchunk * 4 + ntl) * 128 + wn * 32 + tig * 2;
#pragma unroll
                for (int ni = 0; ni < 4; ni++) {
                    const int c0 = colb + ni * 8;
                    float2 nh = *reinterpret_cast<const float2*>(&g_nhn[c0]);
#pragma unroll
                    for (int mi = 0; mi < 4; mi++) {
                        float s0 = acc[mi][ni][0] + nh.x;
                        float s1 = acc[mi][ni][1] + nh.y;
                        float s2 = acc[mi][ni][2] + nh.x;
                        float s3 = acc[mi][ni][3] + nh.y;
                        const int lo = mi * 2, hi = mi * 2 + 1;
                        if (s0 > bestv[lo]) { bestv[lo] = s0; bidxv[lo] = c0; }
                        if (s1 > bestv[lo]) { bestv[lo] = s1; bidxv[lo] = c0 + 1; }
                        if (s2 > bestv[hi]) { bestv[hi] = s2; bidxv[hi] = c0; }
                        if (s3 > bestv[hi]) { bestv[hi] = s3; bidxv[hi] = c0 + 1; }
                    }
                }
            }
        }

#pragma unroll
        for (int s = 0; s < 8; s++) {
#pragma unroll
            for (int d = 1; d < 4; d <<= 1) {
                float ov = __shfl_xor_sync(0xffffffffu, bestv[s], d);
                int   oi = __shfl_xor_sync(0xffffffffu, bidxv[s], d);
                if (ov > bestv[s] || (ov == bestv[s] && oi < bidxv[s])) {
                    bestv[s] = ov; bidxv[s] = oi;
                }
            }
        }
        __syncthreads();
        float* redv = reinterpret_cast<float*>(smem + 32768);
        int*   redi = reinterpret_cast<int*>(smem + 32768 + 2048);
        if (tig == 0) {
#pragma unroll
            for (int s = 0; s < 8; s++) {
                int row = wm * 64 + (s >> 1) * 16 + g + (s & 1) * 8;
                redv[row * 4 + wn] = bestv[s];
                redi[row * 4 + wn] = bidxv[s];
            }
        }
        __syncthreads();
        if (tid < BM && mt * BM + tid < cnt) {
            float bv = redv[tid * 4];
            int   bi = redi[tid * 4];
#pragma unroll
            for (int j = 1; j < 4; j++) {
                float v  = redv[tid * 4 + j];
                int   ii = redi[tid * 4 + j];
                if (v > bv || (v == bv && ii < bi)) { bv = v; bi = ii; }
            }
            unsigned long long packed =
                ((unsigned long long)fkey(bv) << 32) | (unsigned)(4095 - bi);
            atomicMax(&g_best[mt * BM + tid], packed);
        }
        __syncthreads();

        // ---- last-arriving chunk for this m-tile performs writeback -------
        if (tid == 0) {
            __threadfence();
            int r = atomicAdd(&g_done[mt], 1);
            s_last = (r == 7) ? 1 : 0;
        }
        __syncthreads();
        if (s_last) {
            __threadfence();
            int li = mt * BM + (tid >> 1);
            if (li < cnt) {
                int row = g_flag[li];
                unsigned long long p = g_best[li];
                int idx = 4095 - (int)(p & 0xFFFu);
                int half = tid & 1;
                if (half == 0 && out_ind) out_ind[row] = (float)idx;
                const float4* e4 =
                    reinterpret_cast<const float4*>(embed + (size_t)idx * DIM) + half * 8;
                float4* o4 =
                    reinterpret_cast<float4*>(outq + (size_t)row * DIM) + half * 8;
#pragma unroll
                for (int j = 0; j < 8; j++) o4[j] = e4[j];
            }
        }
        __syncthreads();
    }
}

// Defensive tail fill (launched only when a tail exists).
__global__ void fill_kernel(float* __restrict__ out, int start, int end) {
    int i = start + blockIdx.x * blockDim.x + threadIdx.x;
    if (i < end) out[i] = 0.f;
}

// ---------------------------------------------------------------------------
extern "C" void kernel_launch(void* const* d_in, const int* in_sizes, int n_in,
                              void* d_out, int out_size) {
    const float* x     = (const float*)d_in[0];
    const float* embed = (const float*)d_in[1];
    float* out = (float*)d_out;

    const int M = in_sizes[0] / DIM;  // 32768

    prep_kernel<<<128, 256>>>(embed);

    cudaFuncSetAttribute(vq_pass1,
                         cudaFuncAttributeMaxDynamicSharedMemorySize, P1_SMEM);
    cudaFuncSetAttribute(vq_rescore,
                         cudaFuncAttributeMaxDynamicSharedMemorySize, RS_SMEM);

    float* oind = (out_size >= M * DIM + M) ? (out + (size_t)M * DIM) : nullptr;
    vq_pass1<<<M / BM, 256, P1_SMEM>>>(x, embed, out, oind);
    vq_rescore<<<dim3(8, 16), 256, RS_SMEM>>>(x, embed, out, oind);

    int written = M * DIM + (oind ? M : 0);
    if (out_size > written) {
        int tail = out_size - written;
        fill_kernel<<<(tail + 255) / 256, 256>>>(out, written, out_size);
    }
}

// round 12
// speedup vs baseline: 1.1334x; 1.1334x over previous
#include <cuda_runtime.h>
#include <cuda_fp16.h>
#include <cstdint>
#include <cstddef>

#define DIM   64
#define CBK   4096
#define MAXM  32768
#define KU    128            // rescore slices [h1|h2]
#define BM    128
#define TAU   0.15f
#define CAP   16384
#define BIAS  512.0f

// ---------------------------------------------------------------------------
// Device scratch (static)
// ---------------------------------------------------------------------------
__device__ float g_nhn[CBK];                                   // 512 - 0.5*||e||^2
__device__ __align__(256) __half g_es[(size_t)CBK * KU];       // e: h1|h2 (rescore)
__device__ __align__(256) uint4 g_e1f4[32768];                 // e1 frags, j-paired
__device__ int g_cnt;
__device__ int g_done[CAP / BM];
__device__ int g_flag[CAP];
__device__ unsigned long long g_best[CAP];

// ---------------------------------------------------------------------------
// PTX helpers
// ---------------------------------------------------------------------------
__device__ __forceinline__ uint32_t smem_u32(const void* p) {
    uint32_t a;
    asm("{ .reg .u64 t; cvta.to.shared.u64 t, %1; cvt.u32.u64 %0, t; }"
        : "=r"(a) : "l"(p));
    return a;
}
__device__ __forceinline__ void cp16(uint32_t dst, const void* src) {
    asm volatile("cp.async.cg.shared.global [%0], [%1], 16;" :: "r"(dst), "l"(src));
}
__device__ __forceinline__ void cp_commit() {
    asm volatile("cp.async.commit_group;");
}
#define CP_WAIT(n) asm volatile("cp.async.wait_group %0;" :: "n"(n) : "memory")
__device__ __forceinline__ void ldsm4(uint32_t* r, uint32_t addr) {
    asm volatile("ldmatrix.sync.aligned.m8n8.x4.shared.b16 {%0,%1,%2,%3}, [%4];"
                 : "=r"(r[0]), "=r"(r[1]), "=r"(r[2]), "=r"(r[3]) : "r"(addr));
}
__device__ __forceinline__ void ldsm2(uint32_t* r, uint32_t addr) {
    asm volatile("ldmatrix.sync.aligned.m8n8.x2.shared.b16 {%0,%1}, [%2];"
                 : "=r"(r[0]), "=r"(r[1]) : "r"(addr));
}
__device__ __forceinline__ void hmma(float* d, const uint32_t* a, const uint32_t* b) {
    asm volatile("mma.sync.aligned.m16n8k16.row.col.f32.f16.f16.f32 "
                 "{%0,%1,%2,%3}, {%4,%5,%6,%7}, {%8,%9}, {%0,%1,%2,%3};"
                 : "+f"(d[0]), "+f"(d[1]), "+f"(d[2]), "+f"(d[3])
                 : "r"(a[0]), "r"(a[1]), "r"(a[2]), "r"(a[3]),
                   "r"(b[0]), "r"(b[1]));
}
// D = A*B + {cx, cy, cx, cy}  (accumulator init — D != C form)
__device__ __forceinline__ void hmma_c(float* d, const uint32_t* a, const uint32_t* b,
                                       float cx, float cy) {
    asm volatile("mma.sync.aligned.m16n8k16.row.col.f32.f16.f16.f32 "
                 "{%0,%1,%2,%3}, {%4,%5,%6,%7}, {%8,%9}, {%10,%11,%10,%11};"
                 : "=f"(d[0]), "=f"(d[1]), "=f"(d[2]), "=f"(d[3])
                 : "r"(a[0]), "r"(a[1]), "r"(a[2]), "r"(a[3]),
                   "r"(b[0]), "r"(b[1]), "f"(cx), "f"(cy));
}
__device__ __forceinline__ uint32_t fkey(float f) {
    uint32_t u = __float_as_uint(f);
    return (u & 0x80000000u) ? ~u : (u | 0x80000000u);
}
__device__ __forceinline__ uint32_t umaxu(uint32_t a, uint32_t b) { return a > b ? a : b; }
__device__ __forceinline__ uint32_t uminu(uint32_t a, uint32_t b) { return a < b ? a : b; }

// ---------------------------------------------------------------------------
// Split fp32 -> (h1,h2) fp16.  Exact 3-term score: h1e1 + h1e2 + h2e1.
// ---------------------------------------------------------------------------
__device__ __forceinline__ void split8(float4 lo, float4 hi, uint4* h) {
    float v[8] = {lo.x, lo.y, lo.z, lo.w, hi.x, hi.y, hi.z, hi.w};
    union U { unsigned short s[8]; uint4 u; } u1, u2;
#pragma unroll
    for (int k = 0; k < 8; k++) {
        float a = v[k];
        __half b1 = __float2half_rn(a);
        float r1 = a - __half2float(b1);
        __half b2 = __float2half_rn(r1);
        u1.s[k] = *reinterpret_cast<unsigned short*>(&b1);
        u2.s[k] = *reinterpret_cast<unsigned short*>(&b2);
    }
    h[0] = u1.u; h[1] = u2.u;
}

// h1-only conversion of 8 floats -> uint4 of halves
__device__ __forceinline__ uint4 cvt8(float4 lo, float4 hi) {
    uint4 v;
    __half2 a = __floats2half2_rn(lo.x, lo.y);
    __half2 b = __floats2half2_rn(lo.z, lo.w);
    __half2 c = __floats2half2_rn(hi.x, hi.y);
    __half2 d = __floats2half2_rn(hi.z, hi.w);
    v.x = *reinterpret_cast<uint32_t*>(&a);
    v.y = *reinterpret_cast<uint32_t*>(&b);
    v.z = *reinterpret_cast<uint32_t*>(&c);
    v.w = *reinterpret_cast<uint32_t*>(&d);
    return v;
}

// ---------------------------------------------------------------------------
// Prologue (e-side only): init state, split e (+ biased norms), pack e1 frags.
// ---------------------------------------------------------------------------
__global__ void prep_kernel(const float* __restrict__ e) {
    const int gid = blockIdx.x * blockDim.x + threadIdx.x;

    if (gid == 0) g_cnt = 0;
    if (gid < CAP) g_best[gid] = 0ULL;
    if (gid < CAP / BM) g_done[gid] = 0;

    if (gid < CBK * 8) {
        int row = gid >> 3, c8 = gid & 7;
        const float4* p = reinterpret_cast<const float4*>(e + (size_t)row * DIM + c8 * 8);
        float4 lo = p[0], hi = p[1];
        uint4 h[2];
        split8(lo, hi, h);
        __half* dst = g_es + (size_t)row * KU + c8 * 8;
        *reinterpret_cast<uint4*>(dst)       = h[0];
        *reinterpret_cast<uint4*>(dst + DIM) = h[1];
        float s = lo.x * lo.x + lo.y * lo.y + lo.z * lo.z + lo.w * lo.w
                + hi.x * hi.x + hi.y * hi.y + hi.z * hi.z + hi.w * hi.w;
        s += __shfl_xor_sync(0xffffffffu, s, 1);
        s += __shfl_xor_sync(0xffffffffu, s, 2);
        s += __shfl_xor_sync(0xffffffffu, s, 4);
        if (c8 == 0) g_nhn[row] = BIAS - 0.5f * s;   // biased: uniform shift
    }

    if (gid < 32768) {
        int lane = gid & 31;
        int nf2  = (gid >> 5) & 7;
        int ks   = (gid >> 8) & 3;
        int nt   = gid >> 10;
        int k0 = ks * 16 + (lane & 3) * 2;
        uint4 v;
#pragma unroll
        for (int j = 0; j < 2; j++) {
            int n = nt * 128 + (nf2 * 2 + j) * 8 + (lane >> 2);
            const float* er = e + (size_t)n * DIM;
            __half2 b0 = __floats2half2_rn(er[k0], er[k0 + 1]);
            __half2 b1 = __floats2half2_rn(er[k0 + 8], er[k0 + 9]);
            if (j == 0) { v.x = *reinterpret_cast<uint32_t*>(&b0);
                          v.y = *reinterpret_cast<uint32_t*>(&b1); }
            else        { v.z = *reinterpret_cast<uint32_t*>(&b0);
                          v.w = *reinterpret_cast<uint32_t*>(&b1); }
        }
        g_e1f4[gid] = v;
    }
}

// ---------------------------------------------------------------------------
// Pass 1: single-term fp16 GEMM (h1 . e1), nh (biased) folded into the MMA C
// operand via SMEM; branch-free packed-key top-2 epilogue.
// SMEM: [0,16K) A tile (swizzled h1), [16K,32K) nh table.
// ---------------------------------------------------------------------------
#define P1_SMEM 32768

__global__ __launch_bounds__(256, 2)
void vq_pass1(const float* __restrict__ x,
              const float* __restrict__ embed,
              float* __restrict__ outq,
              float* __restrict__ out_ind) {
    extern __shared__ __align__(128) char smem[];
    const uint32_t As_u = smem_u32(smem);
    const uint32_t Nh_u = As_u + 16384;

    const int tid  = threadIdx.x;
    const int lane = tid & 31, wid = tid >> 5;
    const int wm = wid & 1, wn = wid >> 1;
    const int g = lane >> 2, tig = lane & 3;
    const int mtile = blockIdx.x;

    // ---- Prologue: A tile (fp32 x -> h1, swizzled) + nh table --------------
    {
        const float* xa = x + (size_t)mtile * BM * DIM;
#pragma unroll
        for (int i = 0; i < 4; i++) {
            int idx = tid + i * 256;
            int row = idx >> 3, c = idx & 7;
            const float* src = xa + (size_t)row * DIM + c * 8;
            float4 lo = __ldg(reinterpret_cast<const float4*>(src));
            float4 hi = __ldg(reinterpret_cast<const float4*>(src + 4));
            *reinterpret_cast<uint4*>(smem + row * 128 + ((c ^ (row & 7)) << 4)) =
                cvt8(lo, hi);
        }
#pragma unroll
        for (int i = 0; i < 4; i++) {
            int idx = tid + i * 256;   // 1024 float4 = 4096 floats
            *reinterpret_cast<float4*>(smem + 16384 + idx * 16) =
                __ldg(reinterpret_cast<const float4*>(g_nhn) + idx);
        }
    }

    uint32_t aBase[4];
#pragma unroll
    for (int mi = 0; mi < 4; mi++)
        aBase[mi] = As_u + (wm * 64 + mi * 16 + (lane & 15)) * 128;
    const uint32_t amask = (lane & 7) << 4;
    const uint32_t asel  = lane >> 4;

    const uint4* bp4 = g_e1f4 + (size_t)(wn * 2) * 32 + lane;

    uint32_t b1u[8], b2u[8];
#pragma unroll
    for (int s = 0; s < 8; s++) { b1u[s] = 0u; b2u[s] = 0u; }

    __syncthreads();

    auto loadB = [&](int u, uint4 (&bf)[4]) {
        const int nt = u >> 1, h = u & 1;
        const uint4* p = bp4 + (size_t)nt * 1024 + h * 32;
#pragma unroll
        for (int ks = 0; ks < 4; ks++) bf[ks] = __ldg(p + ks * 256);
    };
    auto computeH = [&](int u, uint4 (&bf)[4]) {
        const int nt = u >> 1, h = u & 1;
        const int colb = nt * 128 + wn * 32 + h * 16 + tig * 2;
        // nh from SMEM (29-cyc LDS, off the global-memory critical path)
        const float2 nh0 = *reinterpret_cast<const float2*>(smem + 16384 + colb * 4);
        const float2 nh1 = *reinterpret_cast<const float2*>(smem + 16384 + (colb + 8) * 4);
        float acc[4][2][4];
        {   // ks = 0: accumulator initialized with biased nh via C operand
            uint32_t a[4][4];
            const uint32_t aoff = ((uint32_t)asel << 4) ^ amask;
#pragma unroll
            for (int mi = 0; mi < 4; mi++) ldsm4(a[mi], aBase[mi] + aoff);
            const uint32_t* bw = reinterpret_cast<const uint32_t*>(&bf[0]);
#pragma unroll
            for (int mi = 0; mi < 4; mi++) {
                hmma_c(acc[mi][0], a[mi], bw,     nh0.x, nh0.y);
                hmma_c(acc[mi][1], a[mi], bw + 2, nh1.x, nh1.y);
            }
        }
#pragma unroll
        for (int ks = 1; ks < 4; ks++) {
            uint32_t a[4][4];
            const uint32_t aoff = (((uint32_t)(ks * 2) + asel) << 4) ^ amask;
#pragma unroll
            for (int mi = 0; mi < 4; mi++) ldsm4(a[mi], aBase[mi] + aoff);
            const uint32_t* bw = reinterpret_cast<const uint32_t*>(&bf[ks]);
#pragma unroll
            for (int mi = 0; mi < 4; mi++) {
                hmma(acc[mi][0], a[mi], bw);
                hmma(acc[mi][1], a[mi], bw + 2);
            }
        }
        // ---- branch-free packed-key top-2 (scores positive: bias=512) -----
        const uint32_t base_ord = (uint32_t)u << 2;
#pragma unroll
        for (int j = 0; j < 2; j++) {
            const uint32_t orda = base_ord + j * 2;
            const uint32_t ordb = orda + 1;
#pragma unroll
            for (int mi = 0; mi < 4; mi++) {
                const int lo = mi * 2, hi = mi * 2 + 1;
                uint32_t k0 = (__float_as_uint(acc[mi][j][0]) & 0xFFFFFF00u) | orda;
                uint32_t k1 = (__float_as_uint(acc[mi][j][1]) & 0xFFFFFF00u) | ordb;
                uint32_t k2 = (__float_as_uint(acc[mi][j][2]) & 0xFFFFFF00u) | orda;
                uint32_t k3 = (__float_as_uint(acc[mi][j][3]) & 0xFFFFFF00u) | ordb;
                b2u[lo] = umaxu(b2u[lo], uminu(b1u[lo], k0)); b1u[lo] = umaxu(b1u[lo], k0);
                b2u[lo] = umaxu(b2u[lo], uminu(b1u[lo], k1)); b1u[lo] = umaxu(b1u[lo], k1);
                b2u[hi] = umaxu(b2u[hi], uminu(b1u[hi], k2)); b1u[hi] = umaxu(b1u[hi], k2);
                b2u[hi] = umaxu(b2u[hi], uminu(b1u[hi], k3)); b1u[hi] = umaxu(b1u[hi], k3);
            }
        }
    };

    uint4 bufA[4], bufB[4];
    loadB(0, bufA);
    for (int u = 0; u < 64; u += 2) {
        loadB(u + 1, bufB);
        computeH(u, bufA);
        if (u + 2 < 64) loadB(u + 2, bufA);
        computeH(u + 1, bufB);
    }

    // ---- decode per-slot winners (before any cross-thread merge) ----------
    float b1[8], b2[8];
    int   i1[8];
#pragma unroll
    for (int s = 0; s < 8; s++) {
        uint32_t key = b1u[s];
        int ord = key & 255;
        int u = ord >> 2, jv = ord & 3;
        i1[s] = (u >> 1) * 128 + wn * 32 + (u & 1) * 16 + tig * 2
              + ((jv >> 1) * 8) + (jv & 1);
        b1[s] = __uint_as_float(key & 0xFFFFFF00u);
        b2[s] = __uint_as_float(b2u[s] & 0xFFFFFF00u);
    }

    // quad reduce (top-2 over disjoint candidate sets)
#pragma unroll
    for (int s = 0; s < 8; s++) {
#pragma unroll
        for (int d = 1; d < 4; d <<= 1) {
            float ov1 = __shfl_xor_sync(0xffffffffu, b1[s], d);
            int   oi1 = __shfl_xor_sync(0xffffffffu, i1[s], d);
            float ov2 = __shfl_xor_sync(0xffffffffu, b2[s], d);
            if (ov1 > b1[s] || (ov1 == b1[s] && oi1 < i1[s])) {
                b2[s] = fmaxf(b1[s], ov2); b1[s] = ov1; i1[s] = oi1;
            } else {
                b2[s] = fmaxf(b2[s], ov1);
            }
        }
    }
    __syncthreads();
    float* rv1 = reinterpret_cast<float*>(smem);
    int*   ri1 = reinterpret_cast<int*>(smem + 2048);
    float* rv2 = reinterpret_cast<float*>(smem + 4096);
    if (tig == 0) {
#pragma unroll
        for (int s = 0; s < 8; s++) {
            int row = wm * 64 + (s >> 1) * 16 + g + (s & 1) * 8;
            rv1[row * 4 + wn] = b1[s];
            ri1[row * 4 + wn] = i1[s];
            rv2[row * 4 + wn] = b2[s];
        }
    }
    __syncthreads();

    if (tid < BM) {
        float B1 = rv1[tid * 4], B2 = rv2[tid * 4];
        int   I1 = ri1[tid * 4];
#pragma unroll
        for (int j = 1; j < 4; j++) {
            float a1 = rv1[tid * 4 + j], a2 = rv2[tid * 4 + j];
            int   ai = ri1[tid * 4 + j];
            if (a1 > B1 || (a1 == B1 && ai < I1)) {
                B2 = fmaxf(B1, a2); B1 = a1; I1 = ai;
            } else {
                B2 = fmaxf(B2, a1);
            }
        }
        const int grow = mtile * BM + tid;
        if (out_ind) out_ind[grow] = (float)I1;
        const float4* e4 = reinterpret_cast<const float4*>(embed + (size_t)I1 * DIM);
        float4* o4 = reinterpret_cast<float4*>(outq + (size_t)grow * DIM);
#pragma unroll
        for (int i = 0; i < DIM / 4; i++) o4[i] = e4[i];
        if (B1 - B2 < TAU) {
            int pos = atomicAdd(&g_cnt, 1);
            if (pos < CAP) g_flag[pos] = grow;
        }
    }
}

// ---------------------------------------------------------------------------
// Rescore (exact 3-term) over flagged rows; A re-split from fp32 x inline.
// 8 codebook chunks x m-tiles; last-finishing chunk per tile writes back.
// (g_nhn bias shifts all scores uniformly -> argmax invariant.)
// ---------------------------------------------------------------------------
#define RS_SMEM (32768 + 65536)

template<int TERMS>
__device__ __forceinline__ void compute_stage(
    float (&acc)[4][4][4], const uint32_t* aBase, uint32_t amask, uint32_t asel,
    uint32_t bst, const uint32_t* bOff, uint32_t bmask, uint32_t bsel)
{
#pragma unroll
    for (int ks = 0; ks < 4; ks++) {
        uint32_t b[4][2];
        const uint32_t boff = (((uint32_t)(ks * 2) + bsel) << 4) ^ bmask;
#pragma unroll
        for (int ni = 0; ni < 4; ni++) ldsm2(b[ni], bst + bOff[ni] + boff);
        const uint32_t aoff = (((uint32_t)(ks * 2) + asel) << 4) ^ amask;
#pragma unroll
        for (int t = 0; t < TERMS; t++) {
            uint32_t a[4][4];
#pragma unroll
            for (int mi = 0; mi < 4; mi++)
                ldsm4(a[mi], aBase[mi] + t * 16384 + aoff);
#pragma unroll
            for (int mi = 0; mi < 4; mi++)
#pragma unroll
                for (int ni = 0; ni < 4; ni++)
                    hmma(acc[mi][ni], a[mi], b[ni]);
        }
    }
}

__global__ __launch_bounds__(256, 2)
void vq_rescore(const float* __restrict__ x,
                const float* __restrict__ embed,
                float* __restrict__ outq,
                float* __restrict__ out_ind) {
    int cnt = g_cnt; if (cnt > CAP) cnt = CAP;
    extern __shared__ __align__(128) char smem[];
    __shared__ int s_last;
    const uint32_t As_u = smem_u32(smem);
    const uint32_t Bs_u = As_u + 32768;

    const int tid  = threadIdx.x;
    const int lane = tid & 31, wid = tid >> 5;
    const int wm = wid & 1, wn = wid >> 1;
    const int g = lane >> 2, tig = lane & 3;
    const int nchunk = blockIdx.x;

    uint32_t aBase[4];
#pragma unroll
    for (int mi = 0; mi < 4; mi++)
        aBase[mi] = As_u + (wm * 64 + mi * 16 + (lane & 15)) * 128;
    const uint32_t amask = (lane & 7) << 4;
    const uint32_t asel  = lane >> 4;
    uint32_t bOff[4];
#pragma unroll
    for (int ni = 0; ni < 4; ni++)
        bOff[ni] = (wn * 32 + ni * 8 + (lane & 7)) * 128;
    const uint32_t bmask = (lane & 7) << 4;
    const uint32_t bsel  = (lane >> 3) & 1;

    auto prefetchB = [&](int st, int slot) {
        const int nt = nchunk * 4 + (st >> 1), s = st & 1;
        const __half* src = g_es + (size_t)nt * BM * KU + s * DIM;
        const uint32_t dbase = Bs_u + slot * 16384;
#pragma unroll
        for (int i = 0; i < 4; i++) {
            int idx = tid + i * 256;
            int row = idx >> 3, c = idx & 7;
            cp16(dbase + row * 128 + ((c ^ (row & 7)) << 4),
                 src + (size_t)row * KU + c * 8);
        }
    };

    for (int mt = blockIdx.y; mt * BM < cnt; mt += gridDim.y) {
#pragma unroll
        for (int i = 0; i < 4; i++) {
            int idx = tid + i * 256;
            int row = idx >> 3, c = idx & 7;
            int ci = mt * BM + row; if (ci >= cnt) ci = cnt - 1;
            int grow = g_flag[ci];
            const float* src = x + (size_t)grow * DIM + c * 8;
            float4 lo = __ldg(reinterpret_cast<const float4*>(src));
            float4 hi = __ldg(reinterpret_cast<const float4*>(src + 4));
            uint4 h[2];
            split8(lo, hi, h);
            uint32_t off = row * 128 + ((c ^ (row & 7)) << 4);
            *reinterpret_cast<uint4*>(smem + off)         = h[0];
            *reinterpret_cast<uint4*>(smem + 16384 + off) = h[1];
        }
        prefetchB(0, 0); cp_commit();
        prefetchB(1, 1); cp_commit();
        prefetchB(2, 2); cp_commit();

        float bestv[8]; int bidxv[8];
#pragma unroll
        for (int s = 0; s < 8; s++) { bestv[s] = -3.402823466e38f; bidxv[s] = 0; }
        float acc[4][4][4];

        for (int si = 0; si < 8; si++) {
            const int cs = si & 1, ntl = si >> 1;
            CP_WAIT(2);
            __syncthreads();
            if (si < 5) prefetchB(si + 3, (si + 3) & 3);
            cp_commit();

            if (cs == 0) {
#pragma unroll
                for (int mi = 0; mi < 4; mi++)
#pragma unroll
                    for (int ni = 0; ni < 4; ni++)
#pragma unroll
                        for (int r = 0; r < 4; r++) acc[mi][ni][r] = 0.f;
            }
            const uint32_t bst = Bs_u + (si & 3) * 16384;
            if (cs == 0) compute_stage<2>(acc, aBase, amask, asel, bst, bOff, bmask, bsel);
            else         compute_stage<1>(acc, aBase, amask, asel, bst, bOff, bmask, bsel);

            if (cs == 1) {
                const int colb = (nchunk * 4 + ntl) * 128 + wn * 32 + tig * 2;
#pragma unroll
                for (int ni = 0; ni < 4; ni++) {
                    const int c0 = colb + ni * 8;
                    float2 nh = *reinterpret_cast<const float2*>(&g_nhn[c0]);
#pragma unroll
                    for (int mi = 0; mi < 4; mi++) {
                        float s0 = acc[mi][ni][0] + nh.x;
                        float s1 = acc[mi][ni][1] + nh.y;
                        float s2 = acc[mi][ni][2] + nh.x;
                        float s3 = acc[mi][ni][3] + nh.y;
                        const int lo = mi * 2, hi = mi * 2 + 1;
                        if (s0 > bestv[lo]) { bestv[lo] = s0; bidxv[lo] = c0; }
                        if (s1 > bestv[lo]) { bestv[lo] = s1; bidxv[lo] = c0 + 1; }
                        if (s2 > bestv[hi]) { bestv[hi] = s2; bidxv[hi] = c0; }
                        if (s3 > bestv[hi]) { bestv[hi] = s3; bidxv[hi] = c0 + 1; }
                    }
                }
            }
        }

#pragma unroll
        for (int s = 0; s < 8; s++) {
#pragma unroll
            for (int d = 1; d < 4; d <<= 1) {
                float ov = __shfl_xor_sync(0xffffffffu, bestv[s], d);
                int   oi = __shfl_xor_sync(0xffffffffu, bidxv[s], d);
                if (ov > bestv[s] || (ov == bestv[s] && oi < bidxv[s])) {
                    bestv[s] = ov; bidxv[s] = oi;
                }
            }
        }
        __syncthreads();
        float* redv = reinterpret_cast<float*>(smem + 32768);
        int*   redi = reinterpret_cast<int*>(smem + 32768 + 2048);
        if (tig == 0) {
#pragma unroll
            for (int s = 0; s < 8; s++) {
                int row = wm * 64 + (s >> 1) * 16 + g + (s & 1) * 8;
                redv[row * 4 + wn] = bestv[s];
                redi[row * 4 + wn] = bidxv[s];
            }
        }
        __syncthreads();
        if (tid < BM && mt * BM + tid < cnt) {
            float bv = redv[tid * 4];
            int   bi = redi[tid * 4];
#pragma unroll
            for (int j = 1; j < 4; j++) {
                float v  = redv[tid * 4 + j];
                int   ii = redi[tid * 4 + j];
                if (v > bv || (v == bv && ii < bi)) { bv = v; bi = ii; }
            }
            unsigned long long packed =
                ((unsigned long long)fkey(bv) << 32) | (unsigned)(4095 - bi);
            atomicMax(&g_best[mt * BM + tid], packed);
        }
        __syncthreads();

        if (tid == 0) {
            __threadfence();
            int r = atomicAdd(&g_done[mt], 1);
            s_last = (r == 7) ? 1 : 0;
        }
        __syncthreads();
        if (s_last) {
            __threadfence();
            int li = mt * BM + (tid >> 1);
            if (li < cnt) {
                int row = g_flag[li];
                unsigned long long p = g_best[li];
                int idx = 4095 - (int)(p & 0xFFFu);
                int half = tid & 1;
                if (half == 0 && out_ind) out_ind[row] = (float)idx;
                const float4* e4 =
                    reinterpret_cast<const float4*>(embed + (size_t)idx * DIM) + half * 8;
                float4* o4 =
                    reinterpret_cast<float4*>(outq + (size_t)row * DIM) + half * 8;
#pragma unroll
                for (int j = 0; j < 8; j++) o4[j] = e4[j];
            }
        }
        __syncthreads();
    }
}

// Defensive tail fill (launched only when a tail exists).
__global__ void fill_kernel(float* __restrict__ out, int start, int end) {
    int i = start + blockIdx.x * blockDim.x + threadIdx.x;
    if (i < end) out[i] = 0.f;
}

// ---------------------------------------------------------------------------
extern "C" void kernel_launch(void* const* d_in, const int* in_sizes, int n_in,
                              void* d_out, int out_size) {
    const float* x     = (const float*)d_in[0];
    const float* embed = (const float*)d_in[1];
    float* out = (float*)d_out;

    const int M = in_sizes[0] / DIM;  // 32768

    prep_kernel<<<128, 256>>>(embed);

    cudaFuncSetAttribute(vq_pass1,
                         cudaFuncAttributeMaxDynamicSharedMemorySize, P1_SMEM);
    cudaFuncSetAttribute(vq_rescore,
                         cudaFuncAttributeMaxDynamicSharedMemorySize, RS_SMEM);

    float* oind = (out_size >= M * DIM + M) ? (out + (size_t)M * DIM) : nullptr;
    vq_pass1<<<M / BM, 256, P1_SMEM>>>(x, embed, out, oind);
    vq_rescore<<<dim3(8, 16), 256, RS_SMEM>>>(x, embed, out, oind);

    int written = M * DIM + (oind ? M : 0);
    if (out_size > written) {
        int tail = out_size - written;
        fill_kernel<<<(tail + 255) / 256, 256>>>(out, written, out_size);
    }
}

// round 15
// speedup vs baseline: 1.2001x; 1.0589x over previous
#include <cuda_runtime.h>
#include <cuda_fp16.h>
#include <cstdint>
#include <cstddef>

#define DIM   64
#define CBK   4096
#define MAXM  32768
#define KU    128            // rescore slices [h1|h2]
#define BM    128
#define TAU   0.20f
#define CAP   16384
#define BIAS  512.0f

// ---------------------------------------------------------------------------
// Device scratch (static)
// ---------------------------------------------------------------------------
__device__ float g_nhn[CBK];                                   // 512 - 0.5*||e||^2
__device__ __align__(256) __half g_es[(size_t)CBK * KU];       // e: h1|h2
__device__ int g_cnt;
__device__ int g_done[CAP / BM];
__device__ int g_flag[CAP];
__device__ unsigned long long g_best[CAP];

// ---------------------------------------------------------------------------
// PTX helpers
// ---------------------------------------------------------------------------
__device__ __forceinline__ uint32_t smem_u32(const void* p) {
    uint32_t a;
    asm("{ .reg .u64 t; cvta.to.shared.u64 t, %1; cvt.u32.u64 %0, t; }"
        : "=r"(a) : "l"(p));
    return a;
}
__device__ __forceinline__ void cp16(uint32_t dst, const void* src) {
    asm volatile("cp.async.cg.shared.global [%0], [%1], 16;" :: "r"(dst), "l"(src));
}
__device__ __forceinline__ void cp_commit() {
    asm volatile("cp.async.commit_group;");
}
#define CP_WAIT(n) asm volatile("cp.async.wait_group %0;" :: "n"(n) : "memory")
__device__ __forceinline__ void ldsm4(uint32_t* r, uint32_t addr) {
    asm volatile("ldmatrix.sync.aligned.m8n8.x4.shared.b16 {%0,%1,%2,%3}, [%4];"
                 : "=r"(r[0]), "=r"(r[1]), "=r"(r[2]), "=r"(r[3]) : "r"(addr));
}
__device__ __forceinline__ void ldsm2(uint32_t* r, uint32_t addr) {
    asm volatile("ldmatrix.sync.aligned.m8n8.x2.shared.b16 {%0,%1}, [%2];"
                 : "=r"(r[0]), "=r"(r[1]) : "r"(addr));
}
__device__ __forceinline__ void hmma(float* d, const uint32_t* a, const uint32_t* b) {
    asm volatile("mma.sync.aligned.m16n8k16.row.col.f32.f16.f16.f32 "
                 "{%0,%1,%2,%3}, {%4,%5,%6,%7}, {%8,%9}, {%0,%1,%2,%3};"
                 : "+f"(d[0]), "+f"(d[1]), "+f"(d[2]), "+f"(d[3])
                 : "r"(a[0]), "r"(a[1]), "r"(a[2]), "r"(a[3]),
                   "r"(b[0]), "r"(b[1]));
}
// D = A*B + {cx, cy, cx, cy}  (accumulator init — D != C form)
__device__ __forceinline__ void hmma_c(float* d, const uint32_t* a, const uint32_t* b,
                                       float cx, float cy) {
    asm volatile("mma.sync.aligned.m16n8k16.row.col.f32.f16.f16.f32 "
                 "{%0,%1,%2,%3}, {%4,%5,%6,%7}, {%8,%9}, {%10,%11,%10,%11};"
                 : "=f"(d[0]), "=f"(d[1]), "=f"(d[2]), "=f"(d[3])
                 : "r"(a[0]), "r"(a[1]), "r"(a[2]), "r"(a[3]),
                   "r"(b[0]), "r"(b[1]), "f"(cx), "f"(cy));
}
__device__ __forceinline__ uint32_t fkey(float f) {
    uint32_t u = __float_as_uint(f);
    return (u & 0x80000000u) ? ~u : (u | 0x80000000u);
}
__device__ __forceinline__ uint32_t umaxu(uint32_t a, uint32_t b) { return a > b ? a : b; }
__device__ __forceinline__ uint32_t uminu(uint32_t a, uint32_t b) { return a < b ? a : b; }

// ---------------------------------------------------------------------------
// Split fp32 -> (h1,h2) fp16.  Exact 3-term score: h1e1 + h1e2 + h2e1.
// ---------------------------------------------------------------------------
__device__ __forceinline__ void split8(float4 lo, float4 hi, uint4* h) {
    float v[8] = {lo.x, lo.y, lo.z, lo.w, hi.x, hi.y, hi.z, hi.w};
    union U { unsigned short s[8]; uint4 u; } u1, u2;
#pragma unroll
    for (int k = 0; k < 8; k++) {
        float a = v[k];
        __half b1 = __float2half_rn(a);
        float r1 = a - __half2float(b1);
        __half b2 = __float2half_rn(r1);
        u1.s[k] = *reinterpret_cast<unsigned short*>(&b1);
        u2.s[k] = *reinterpret_cast<unsigned short*>(&b2);
    }
    h[0] = u1.u; h[1] = u2.u;
}

// h1-only conversion of 8 floats -> uint4 of halves
__device__ __forceinline__ uint4 cvt8(float4 lo, float4 hi) {
    uint4 v;
    __half2 a = __floats2half2_rn(lo.x, lo.y);
    __half2 b = __floats2half2_rn(lo.z, lo.w);
    __half2 c = __floats2half2_rn(hi.x, hi.y);
    __half2 d = __floats2half2_rn(hi.z, hi.w);
    v.x = *reinterpret_cast<uint32_t*>(&a);
    v.y = *reinterpret_cast<uint32_t*>(&b);
    v.z = *reinterpret_cast<uint32_t*>(&c);
    v.w = *reinterpret_cast<uint32_t*>(&d);
    return v;
}

// ---------------------------------------------------------------------------
// Prologue: init state, split e (+ biased norms).
// ---------------------------------------------------------------------------
__global__ void prep_kernel(const float* __restrict__ e) {
    const int gid = blockIdx.x * blockDim.x + threadIdx.x;

    if (gid == 0) g_cnt = 0;
    if (gid < CAP) g_best[gid] = 0ULL;
    if (gid < CAP / BM) g_done[gid] = 0;

    if (gid < CBK * 8) {
        int row = gid >> 3, c8 = gid & 7;
        const float4* p = reinterpret_cast<const float4*>(e + (size_t)row * DIM + c8 * 8);
        float4 lo = p[0], hi = p[1];
        uint4 h[2];
        split8(lo, hi, h);
        __half* dst = g_es + (size_t)row * KU + c8 * 8;
        *reinterpret_cast<uint4*>(dst)       = h[0];
        *reinterpret_cast<uint4*>(dst + DIM) = h[1];
        float s = lo.x * lo.x + lo.y * lo.y + lo.z * lo.z + lo.w * lo.w
                + hi.x * hi.x + hi.y * hi.y + hi.z * hi.z + hi.w * hi.w;
        s += __shfl_xor_sync(0xffffffffu, s, 1);
        s += __shfl_xor_sync(0xffffffffu, s, 2);
        s += __shfl_xor_sync(0xffffffffu, s, 4);
        if (c8 == 0) g_nhn[row] = BIAS - 0.5f * s;   // biased: uniform shift
    }
}

// ---------------------------------------------------------------------------
// Pass 1: single-term fp16 GEMM (h1 . e1).
//  - A fragments hoisted into registers ONCE (u-invariant!)
//  - B staged via cp.async 4-slot ring, consumed by ldsm2 (2-cyc crossbar)
//  - nh folded into MMA C operand (SMEM table)
//  - branch-free packed-key top-2 (9-bit ordinal)
// Warps: wm = wid&3 (32 rows), wn = wid>>2 (64 cols).
// SMEM: [0,16K) A (swizzled h1), [16K,32K) nh, [32K,96K) B ring 4x16K.
// ---------------------------------------------------------------------------
#define P1_SMEM 98304

__global__ __launch_bounds__(256, 2)
void vq_pass1(const float* __restrict__ x,
              const float* __restrict__ embed,
              float* __restrict__ outq,
              float* __restrict__ out_ind) {
    extern __shared__ __align__(128) char smem[];
    const uint32_t As_u = smem_u32(smem);
    const uint32_t Bs_u = As_u + 32768;

    const int tid  = threadIdx.x;
    const int lane = tid & 31, wid = tid >> 5;
    const int wm = wid & 3, wn = wid >> 2;
    const int g = lane >> 2, tig = lane & 3;
    const int mtile = blockIdx.x;

    auto prefetchB = [&](int nt, int slot) {
        const __half* src = g_es + (size_t)nt * BM * KU;       // slice h1 = e1
        const uint32_t dbase = Bs_u + slot * 16384;
#pragma unroll
        for (int i = 0; i < 4; i++) {
            int idx = tid + i * 256;
            int row = idx >> 3, c = idx & 7;
            cp16(dbase + row * 128 + ((c ^ (row & 7)) << 4),
                 src + (size_t)row * KU + c * 8);
        }
    };

    // ---- Prologue: A (fp32 x -> h1, swizzled), nh table, B stages 0-2 -----
    {
        const float* xa = x + (size_t)mtile * BM * DIM;
#pragma unroll
        for (int i = 0; i < 4; i++) {
            int idx = tid + i * 256;
            int row = idx >> 3, c = idx & 7;
            const float* src = xa + (size_t)row * DIM + c * 8;
            float4 lo = __ldg(reinterpret_cast<const float4*>(src));
            float4 hi = __ldg(reinterpret_cast<const float4*>(src + 4));
            *reinterpret_cast<uint4*>(smem + row * 128 + ((c ^ (row & 7)) << 4)) =
                cvt8(lo, hi);
        }
#pragma unroll
        for (int i = 0; i < 4; i++) {
            int idx = tid + i * 256;
            *reinterpret_cast<float4*>(smem + 16384 + idx * 16) =
                __ldg(reinterpret_cast<const float4*>(g_nhn) + idx);
        }
        prefetchB(0, 0); cp_commit();
        prefetchB(1, 1); cp_commit();
        prefetchB(2, 2); cp_commit();
    }

    const uint32_t amask = (lane & 7) << 4;
    const uint32_t asel  = lane >> 4;
    const uint32_t bmask = (lane & 7) << 4;
    const uint32_t bsel  = (lane >> 3) & 1;

    __syncthreads();   // A tile + nh visible

    // ---- Hoist A fragments: 2 mi x 4 ks, loaded ONCE ----------------------
    uint32_t ah[2][4][4];
#pragma unroll
    for (int mi = 0; mi < 2; mi++) {
        uint32_t aBase = As_u + (wm * 32 + mi * 16 + (lane & 15)) * 128;
#pragma unroll
        for (int ks = 0; ks < 4; ks++)
            ldsm4(ah[mi][ks], aBase + ((((uint32_t)(ks * 2) + asel) << 4) ^ amask));
    }

    uint32_t b1u[4], b2u[4];
#pragma unroll
    for (int s = 0; s < 4; s++) { b1u[s] = 0u; b2u[s] = 0u; }

    // ---- Mainloop: 32 nt stages, 2 col-halves each ------------------------
    for (int nt = 0; nt < 32; nt++) {
        CP_WAIT(2);
        __syncthreads();
        if (nt < 29) prefetchB(nt + 3, (nt + 3) & 3);
        cp_commit();

        const uint32_t bst = Bs_u + (nt & 3) * 16384;
#pragma unroll
        for (int half = 0; half < 2; half++) {
            const int colb = nt * 128 + wn * 64 + half * 32 + tig * 2;
            float acc[2][4][4];
            {   // ks = 0: acc initialized with biased nh via C operand
                const uint32_t boff = ((bsel) << 4) ^ bmask;
#pragma unroll
                for (int ni = 0; ni < 4; ni++) {
                    uint32_t b[2];
                    ldsm2(b, bst + (wn * 64 + half * 32 + ni * 8 + (lane & 7)) * 128 + boff);
                    const float2 nh = *reinterpret_cast<const float2*>(
                        smem + 16384 + (colb + ni * 8) * 4);
                    hmma_c(acc[0][ni], ah[0][0], b, nh.x, nh.y);
                    hmma_c(acc[1][ni], ah[1][0], b, nh.x, nh.y);
                }
            }
#pragma unroll
            for (int ks = 1; ks < 4; ks++) {
                const uint32_t boff = (((uint32_t)(ks * 2) + bsel) << 4) ^ bmask;
#pragma unroll
                for (int ni = 0; ni < 4; ni++) {
                    uint32_t b[2];
                    ldsm2(b, bst + (wn * 64 + half * 32 + ni * 8 + (lane & 7)) * 128 + boff);
                    hmma(acc[0][ni], ah[0][ks], b);
                    hmma(acc[1][ni], ah[1][ks], b);
                }
            }
            // ---- packed-key top-2 (9-bit ordinal) -------------------------
            const uint32_t obase = ((uint32_t)nt << 4) | ((uint32_t)half << 3);
#pragma unroll
            for (int ni = 0; ni < 4; ni++) {
                const uint32_t o0 = obase | ((uint32_t)ni << 1);
                const uint32_t o1 = o0 | 1u;
#pragma unroll
                for (int mi = 0; mi < 2; mi++) {
                    const int lo = mi * 2, hi = mi * 2 + 1;
                    uint32_t k0 = (__float_as_uint(acc[mi][ni][0]) & 0xFFFFFE00u) | o0;
                    uint32_t k1 = (__float_as_uint(acc[mi][ni][1]) & 0xFFFFFE00u) | o1;
                    uint32_t k2 = (__float_as_uint(acc[mi][ni][2]) & 0xFFFFFE00u) | o0;
                    uint32_t k3 = (__float_as_uint(acc[mi][ni][3]) & 0xFFFFFE00u) | o1;
                    b2u[lo] = umaxu(b2u[lo], uminu(b1u[lo], k0)); b1u[lo] = umaxu(b1u[lo], k0);
                    b2u[lo] = umaxu(b2u[lo], uminu(b1u[lo], k1)); b1u[lo] = umaxu(b1u[lo], k1);
                    b2u[hi] = umaxu(b2u[hi], uminu(b1u[hi], k2)); b1u[hi] = umaxu(b1u[hi], k2);
                    b2u[hi] = umaxu(b2u[hi], uminu(b1u[hi], k3)); b1u[hi] = umaxu(b1u[hi], k3);
                }
            }
        }
    }

    // ---- decode per-slot winners ------------------------------------------
    float b1[4], b2[4];
    int   i1[4];
#pragma unroll
    for (int s = 0; s < 4; s++) {
        uint32_t key = b1u[s];
        uint32_t ord = key & 511u;
        i1[s] = (int)((ord >> 4) * 128 + wn * 64 + ((ord >> 3) & 1) * 32
                      + ((ord >> 1) & 3) * 8 + tig * 2 + (ord & 1));
        b1[s] = __uint_as_float(key & 0xFFFFFE00u);
        b2[s] = __uint_as_float(b2u[s] & 0xFFFFFE00u);
    }

    // quad reduce (top-2 over disjoint candidate sets)
#pragma unroll
    for (int s = 0; s < 4; s++) {
#pragma unroll
        for (int d = 1; d < 4; d <<= 1) {
            float ov1 = __shfl_xor_sync(0xffffffffu, b1[s], d);
            int   oi1 = __shfl_xor_sync(0xffffffffu, i1[s], d);
            float ov2 = __shfl_xor_sync(0xffffffffu, b2[s], d);
            if (ov1 > b1[s] || (ov1 == b1[s] && oi1 < i1[s])) {
                b2[s] = fmaxf(b1[s], ov2); b1[s] = ov1; i1[s] = oi1;
            } else {
                b2[s] = fmaxf(b2[s], ov1);
            }
        }
    }
    __syncthreads();   // reuse smem for reduction
    float* rv1 = reinterpret_cast<float*>(smem);
    int*   ri1 = reinterpret_cast<int*>(smem + 1024);
    float* rv2 = reinterpret_cast<float*>(smem + 2048);
    if (tig == 0) {
#pragma unroll
        for (int s = 0; s < 4; s++) {
            int row = wm * 32 + (s >> 1) * 16 + (s & 1) * 8 + g;
            rv1[row * 2 + wn] = b1[s];
            ri1[row * 2 + wn] = i1[s];
            rv2[row * 2 + wn] = b2[s];
        }
    }
    __syncthreads();

    if (tid < BM) {
        float B1 = rv1[tid * 2], B2 = rv2[tid * 2];
        int   I1 = ri1[tid * 2];
        {
            float a1 = rv1[tid * 2 + 1], a2 = rv2[tid * 2 + 1];
            int   ai = ri1[tid * 2 + 1];
            if (a1 > B1 || (a1 == B1 && ai < I1)) {
                B2 = fmaxf(B1, a2); B1 = a1; I1 = ai;
            } else {
                B2 = fmaxf(B2, a1);
            }
        }
        const int grow = mtile * BM + tid;
        if (out_ind) out_ind[grow] = (float)I1;
        const float4* e4 = reinterpret_cast<const float4*>(embed + (size_t)I1 * DIM);
        float4* o4 = reinterpret_cast<float4*>(outq + (size_t)grow * DIM);
#pragma unroll
        for (int i = 0; i < DIM / 4; i++) o4[i] = e4[i];
        if (B1 - B2 < TAU) {
            int pos = atomicAdd(&g_cnt, 1);
            if (pos < CAP) g_flag[pos] = grow;
        }
    }
}

// ---------------------------------------------------------------------------
// Rescore (exact 3-term) over flagged rows; A re-split from fp32 x inline.
// 8 codebook chunks x m-tiles; last-finishing chunk per tile writes back.
// ---------------------------------------------------------------------------
#define RS_SMEM (32768 + 65536)

template<int TERMS>
__device__ __forceinline__ void compute_stage(
    float (&acc)[4][4][4], const uint32_t* aBase, uint32_t amask, uint32_t asel,
    uint32_t bst, const uint32_t* bOff, uint32_t bmask, uint32_t bsel)
{
#pragma unroll
    for (int ks = 0; ks < 4; ks++) {
        uint32_t b[4][2];
        const uint32_t boff = (((uint32_t)(ks * 2) + bsel) << 4) ^ bmask;
#pragma unroll
        for (int ni = 0; ni < 4; ni++) ldsm2(b[ni], bst + bOff[ni] + boff);
        const uint32_t aoff = (((uint32_t)(ks * 2) + asel) << 4) ^ amask;
#pragma unroll
        for (int t = 0; t < TERMS; t++) {
            uint32_t a[4][4];
#pragma unroll
            for (int mi = 0; mi < 4; mi++)
                ldsm4(a[mi], aBase[mi] + t * 16384 + aoff);
#pragma unroll
            for (int mi = 0; mi < 4; mi++)
#pragma unroll
                for (int ni = 0; ni < 4; ni++)
                    hmma(acc[mi][ni], a[mi], b[ni]);
        }
    }
}

__global__ __launch_bounds__(256, 2)
void vq_rescore(const float* __restrict__ x,
                const float* __restrict__ embed,
                float* __restrict__ outq,
                float* __restrict__ out_ind) {
    int cnt = g_cnt; if (cnt > CAP) cnt = CAP;
    extern __shared__ __align__(128) char smem[];
    __shared__ int s_last;
    const uint32_t As_u = smem_u32(smem);
    const uint32_t Bs_u = As_u + 32768;

    const int tid  = threadIdx.x;
    const int lane = tid & 31, wid = tid >> 5;
    const int wm = wid & 1, wn = wid >> 1;
    const int g = lane >> 2, tig = lane & 3;
    const int nchunk = blockIdx.x;

    uint32_t aBase[4];
#pragma unroll
    for (int mi = 0; mi < 4; mi++)
        aBase[mi] = As_u + (wm * 64 + mi * 16 + (lane & 15)) * 128;
    const uint32_t amask = (lane & 7) << 4;
    const uint32_t asel  = lane >> 4;
    uint32_t bOff[4];
#pragma unroll
    for (int ni = 0; ni < 4; ni++)
        bOff[ni] = (wn * 32 + ni * 8 + (lane & 7)) * 128;
    const uint32_t bmask = (lane & 7) << 4;
    const uint32_t bsel  = (lane >> 3) & 1;

    auto prefetchB = [&](int st, int slot) {
        const int nt = nchunk * 4 + (st >> 1), s = st & 1;
        const __half* src = g_es + (size_t)nt * BM * KU + s * DIM;
        const uint32_t dbase = Bs_u + slot * 16384;
#pragma unroll
        for (int i = 0; i < 4; i++) {
            int idx = tid + i * 256;
            int row = idx >> 3, c = idx & 7;
            cp16(dbase + row * 128 + ((c ^ (row & 7)) << 4),
                 src + (size_t)row * KU + c * 8);
        }
    };

    for (int mt = blockIdx.y; mt * BM < cnt; mt += gridDim.y) {
#pragma unroll
        for (int i = 0; i < 4; i++) {
            int idx = tid + i * 256;
            int row = idx >> 3, c = idx & 7;
            int ci = mt * BM + row; if (ci >= cnt) ci = cnt - 1;
            int grow = g_flag[ci];
            const float* src = x + (size_t)grow * DIM + c * 8;
            float4 lo = __ldg(reinterpret_cast<const float4*>(src));
            float4 hi = __ldg(reinterpret_cast<const float4*>(src + 4));
            uint4 h[2];
            split8(lo, hi, h);
            uint32_t off = row * 128 + ((c ^ (row & 7)) << 4);
            *reinterpret_cast<uint4*>(smem + off)         = h[0];
            *reinterpret_cast<uint4*>(smem + 16384 + off) = h[1];
        }
        prefetchB(0, 0); cp_commit();
        prefetchB(1, 1); cp_commit();
        prefetchB(2, 2); cp_commit();

        float bestv[8]; int bidxv[8];
#pragma unroll
        for (int s = 0; s < 8; s++) { bestv[s] = -3.402823466e38f; bidxv[s] = 0; }
        float acc[4][4][4];

        for (int si = 0; si < 8; si++) {
            const int cs = si & 1, ntl = si >> 1;
            CP_WAIT(2);
            __syncthreads();
            if (si < 5) prefetchB(si + 3, (si + 3) & 3);
            cp_commit();

            if (cs == 0) {
#pragma unroll
                for (int mi = 0; mi < 4; mi++)
#pragma unroll
                    for (int ni = 0; ni < 4; ni++)
#pragma unroll
                        for (int r = 0; r < 4; r++) acc[mi][ni][r] = 0.f;
            }
            const uint32_t bst = Bs_u + (si & 3) * 16384;
            if (cs == 0) compute_stage<2>(acc, aBase, amask, asel, bst, bOff, bmask, bsel);
            else         compute_stage<1>(acc, aBase, amask, asel, bst, bOff, bmask, bsel);

            if (cs == 1) {
                const int colb = (nchunk * 4 + ntl) * 128 + wn * 32 + tig * 2;
#pragma unroll
                for (int ni = 0; ni < 4; ni++) {
                    const int c0 = colb + ni * 8;
                    float2 nh = *reinterpret_cast<const float2*>(&g_nhn[c0]);
#pragma unroll
                    for (int mi = 0; mi < 4; mi++) {
                        float s0 = acc[mi][ni][0] + nh.x;
                        float s1 = acc[mi][ni][1] + nh.y;
                        float s2 = acc[mi][ni][2] + nh.x;
                        float s3 = acc[mi][ni][3] + nh.y;
                        const int lo = mi * 2, hi = mi * 2 + 1;
                        if (s0 > bestv[lo]) { bestv[lo] = s0; bidxv[lo] = c0; }
                        if (s1 > bestv[lo]) { bestv[lo] = s1; bidxv[lo] = c0 + 1; }
                        if (s2 > bestv[hi]) { bestv[hi] = s2; bidxv[hi] = c0; }
                        if (s3 > bestv[hi]) { bestv[hi] = s3; bidxv[hi] = c0 + 1; }
                    }
                }
            }
        }

#pragma unroll
        for (int s = 0; s < 8; s++) {
#pragma unroll
            for (int d = 1; d < 4; d <<= 1) {
                float ov = __shfl_xor_sync(0xffffffffu, bestv[s], d);
                int   oi = __shfl_xor_sync(0xffffffffu, bidxv[s], d);
                if (ov > bestv[s] || (ov == bestv[s] && oi < bidxv[s])) {
                    bestv[s] = ov; bidxv[s] = oi;
                }
            }
        }
        __syncthreads();
        float* redv = reinterpret_cast<float*>(smem + 32768);
        int*   redi = reinterpret_cast<int*>(smem + 32768 + 2048);
        if (tig == 0) {
#pragma unroll
            for (int s = 0; s < 8; s++) {
                int row = wm * 64 + (s >> 1) * 16 + g + (s & 1) * 8;
                redv[row * 4 + wn] = bestv[s];
                redi[row * 4 + wn] = bidxv[s];
            }
        }
        __syncthreads();
        if (tid < BM && mt * BM + tid < cnt) {
            float bv = redv[tid * 4];
            int   bi = redi[tid * 4];
#pragma unroll
            for (int j = 1; j < 4; j++) {
                float v  = redv[tid * 4 + j];
                int   ii = redi[tid * 4 + j];
                if (v > bv || (v == bv && ii < bi)) { bv = v; bi = ii; }
            }
            unsigned long long packed =
                ((unsigned long long)fkey(bv) << 32) | (unsigned)(4095 - bi);
            atomicMax(&g_best[mt * BM + tid], packed);
        }
        __syncthreads();

        if (tid == 0) {
            __threadfence();
            int r = atomicAdd(&g_done[mt], 1);
            s_last = (r == 7) ? 1 : 0;
        }
        __syncthreads();
        if (s_last) {
            __threadfence();
            int li = mt * BM + (tid >> 1);
            if (li < cnt) {
                int row = g_flag[li];
                unsigned long long p = g_best[li];
                int idx = 4095 - (int)(p & 0xFFFu);
                int half = tid & 1;
                if (half == 0 && out_ind) out_ind[row] = (float)idx;
                const float4* e4 =
                    reinterpret_cast<const float4*>(embed + (size_t)idx * DIM) + half * 8;
                float4* o4 =
                    reinterpret_cast<float4*>(outq + (size_t)row * DIM) + half * 8;
#pragma unroll
                for (int j = 0; j < 8; j++) o4[j] = e4[j];
            }
        }
        __syncthreads();
    }
}

// Defensive tail fill (launched only when a tail exists).
__global__ void fill_kernel(float* __restrict__ out, int start, int end) {
    int i = start + blockIdx.x * blockDim.x + threadIdx.x;
    if (i < end) out[i] = 0.f;
}

// ---------------------------------------------------------------------------
extern "C" void kernel_launch(void* const* d_in, const int* in_sizes, int n_in,
                              void* d_out, int out_size) {
    const float* x     = (const float*)d_in[0];
    const float* embed = (const float*)d_in[1];
    float* out = (float*)d_out;

    const int M = in_sizes[0] / DIM;  // 32768

    prep_kernel<<<128, 256>>>(embed);

    cudaFuncSetAttribute(vq_pass1,
                         cudaFuncAttributeMaxDynamicSharedMemorySize, P1_SMEM);
    cudaFuncSetAttribute(vq_rescore,
                         cudaFuncAttributeMaxDynamicSharedMemorySize, RS_SMEM);

    float* oind = (out_size >= M * DIM + M) ? (out + (size_t)M * DIM) : nullptr;
    vq_pass1<<<M / BM, 256, P1_SMEM>>>(x, embed, out, oind);
    vq_rescore<<<dim3(8, 16), 256, RS_SMEM>>>(x, embed, out, oind);

    int written = M * DIM + (oind ? M : 0);
    if (out_size > written) {
        int tail = out_size - written;
        fill_kernel<<<(tail + 255) / 256, 256>>>(out, written, out_size);
    }
}

// round 17
// speedup vs baseline: 1.2041x; 1.0034x over previous
#include <cuda_runtime.h>
#include <cuda_fp16.h>
#include <cstdint>
#include <cstddef>

#define DIM   64
#define CBK   4096
#define MAXM  32768
#define KU    128            // rescore slices [h1|h2]
#define BM    128
#define TAU   0.20f
#define CAP   16384
#define BIAS  512.0f
#define NMT   (MAXM / BM)    // 256 m-tiles

// ---------------------------------------------------------------------------
// Device scratch (static)
// ---------------------------------------------------------------------------
__device__ float g_nhn[CBK];                                   // 512 - 0.5*||e||^2
__device__ __align__(256) __half g_es[(size_t)CBK * KU];       // e: h1|h2
__device__ int g_cnt;
__device__ int g_done[CAP / BM];
__device__ int g_qdone[NMT];
__device__ int g_flag[CAP];
__device__ unsigned long long g_best[CAP];
// per-(mtile, quarter, row) partial top-2
__device__ float g_pb1[NMT * 4 * BM];
__device__ int   g_pi1[NMT * 4 * BM];
__device__ float g_pb2[NMT * 4 * BM];

// ---------------------------------------------------------------------------
// PTX helpers
// ---------------------------------------------------------------------------
__device__ __forceinline__ uint32_t smem_u32(const void* p) {
    uint32_t a;
    asm("{ .reg .u64 t; cvta.to.shared.u64 t, %1; cvt.u32.u64 %0, t; }"
        : "=r"(a) : "l"(p));
    return a;
}
__device__ __forceinline__ void cp16(uint32_t dst, const void* src) {
    asm volatile("cp.async.cg.shared.global [%0], [%1], 16;" :: "r"(dst), "l"(src));
}
__device__ __forceinline__ void cp_commit() {
    asm volatile("cp.async.commit_group;");
}
#define CP_WAIT(n) asm volatile("cp.async.wait_group %0;" :: "n"(n) : "memory")
__device__ __forceinline__ void ldsm4(uint32_t* r, uint32_t addr) {
    asm volatile("ldmatrix.sync.aligned.m8n8.x4.shared.b16 {%0,%1,%2,%3}, [%4];"
                 : "=r"(r[0]), "=r"(r[1]), "=r"(r[2]), "=r"(r[3]) : "r"(addr));
}
__device__ __forceinline__ void ldsm2(uint32_t* r, uint32_t addr) {
    asm volatile("ldmatrix.sync.aligned.m8n8.x2.shared.b16 {%0,%1}, [%2];"
                 : "=r"(r[0]), "=r"(r[1]) : "r"(addr));
}
__device__ __forceinline__ void hmma(float* d, const uint32_t* a, const uint32_t* b) {
    asm volatile("mma.sync.aligned.m16n8k16.row.col.f32.f16.f16.f32 "
                 "{%0,%1,%2,%3}, {%4,%5,%6,%7}, {%8,%9}, {%0,%1,%2,%3};"
                 : "+f"(d[0]), "+f"(d[1]), "+f"(d[2]), "+f"(d[3])
                 : "r"(a[0]), "r"(a[1]), "r"(a[2]), "r"(a[3]),
                   "r"(b[0]), "r"(b[1]));
}
// D = A*B + {cx, cy, cx, cy}  (accumulator init — D != C form)
__device__ __forceinline__ void hmma_c(float* d, const uint32_t* a, const uint32_t* b,
                                       float cx, float cy) {
    asm volatile("mma.sync.aligned.m16n8k16.row.col.f32.f16.f16.f32 "
                 "{%0,%1,%2,%3}, {%4,%5,%6,%7}, {%8,%9}, {%10,%11,%10,%11};"
                 : "=f"(d[0]), "=f"(d[1]), "=f"(d[2]), "=f"(d[3])
                 : "r"(a[0]), "r"(a[1]), "r"(a[2]), "r"(a[3]),
                   "r"(b[0]), "r"(b[1]), "f"(cx), "f"(cy));
}
__device__ __forceinline__ uint32_t fkey(float f) {
    uint32_t u = __float_as_uint(f);
    return (u & 0x80000000u) ? ~u : (u | 0x80000000u);
}
__device__ __forceinline__ uint32_t umaxu(uint32_t a, uint32_t b) { return a > b ? a : b; }
__device__ __forceinline__ uint32_t uminu(uint32_t a, uint32_t b) { return a < b ? a : b; }

// ---------------------------------------------------------------------------
// Split fp32 -> (h1,h2) fp16.  Exact 3-term score: h1e1 + h1e2 + h2e1.
// ---------------------------------------------------------------------------
__device__ __forceinline__ void split8(float4 lo, float4 hi, uint4* h) {
    float v[8] = {lo.x, lo.y, lo.z, lo.w, hi.x, hi.y, hi.z, hi.w};
    union U { unsigned short s[8]; uint4 u; } u1, u2;
#pragma unroll
    for (int k = 0; k < 8; k++) {
        float a = v[k];
        __half b1 = __float2half_rn(a);
        float r1 = a - __half2float(b1);
        __half b2 = __float2half_rn(r1);
        u1.s[k] = *reinterpret_cast<unsigned short*>(&b1);
        u2.s[k] = *reinterpret_cast<unsigned short*>(&b2);
    }
    h[0] = u1.u; h[1] = u2.u;
}

// h1-only conversion of 8 floats -> uint4 of halves
__device__ __forceinline__ uint4 cvt8(float4 lo, float4 hi) {
    uint4 v;
    __half2 a = __floats2half2_rn(lo.x, lo.y);
    __half2 b = __floats2half2_rn(lo.z, lo.w);
    __half2 c = __floats2half2_rn(hi.x, hi.y);
    __half2 d = __floats2half2_rn(hi.z, hi.w);
    v.x = *reinterpret_cast<uint32_t*>(&a);
    v.y = *reinterpret_cast<uint32_t*>(&b);
    v.z = *reinterpret_cast<uint32_t*>(&c);
    v.w = *reinterpret_cast<uint32_t*>(&d);
    return v;
}

// ---------------------------------------------------------------------------
// Prologue: init state, split e (+ biased norms).
// ---------------------------------------------------------------------------
__global__ void prep_kernel(const float* __restrict__ e) {
    const int gid = blockIdx.x * blockDim.x + threadIdx.x;

    if (gid == 0) g_cnt = 0;
    if (gid < CAP) g_best[gid] = 0ULL;
    if (gid < CAP / BM) g_done[gid] = 0;
    if (gid < NMT) g_qdone[gid] = 0;

    if (gid < CBK * 8) {
        int row = gid >> 3, c8 = gid & 7;
        const float4* p = reinterpret_cast<const float4*>(e + (size_t)row * DIM + c8 * 8);
        float4 lo = p[0], hi = p[1];
        uint4 h[2];
        split8(lo, hi, h);
        __half* dst = g_es + (size_t)row * KU + c8 * 8;
        *reinterpret_cast<uint4*>(dst)       = h[0];
        *reinterpret_cast<uint4*>(dst + DIM) = h[1];
        float s = lo.x * lo.x + lo.y * lo.y + lo.z * lo.z + lo.w * lo.w
                + hi.x * hi.x + hi.y * hi.y + hi.z * hi.z + hi.w * hi.w;
        s += __shfl_xor_sync(0xffffffffu, s, 1);
        s += __shfl_xor_sync(0xffffffffu, s, 2);
        s += __shfl_xor_sync(0xffffffffu, s, 4);
        if (c8 == 0) g_nhn[row] = BIAS - 0.5f * s;   // biased: uniform shift
    }
}

// ---------------------------------------------------------------------------
// Pass 1 (quarter-tile): each CTA = (mtile, q) covers 128 rows x 1024 codes.
//  - A fragments hoisted to registers once; B via cp.async ring + ldsm4 pairs
//  - nh (4KB quarter slice) folded into MMA C operand
//  - branch-free packed-key top-2 (7-bit ordinal)
//  - last-of-4 CTA per mtile merges quarters, writes output, flags margins
// SMEM: [0,16K) A (swizzled h1), [16K,20K) nh slice, [20K,84K) B ring 4x16K.
// ---------------------------------------------------------------------------
#define P1_SMEM 86016

__global__ __launch_bounds__(256, 2)
void vq_pass1(const float* __restrict__ x,
              const float* __restrict__ embed,
              float* __restrict__ outq,
              float* __restrict__ out_ind) {
    extern __shared__ __align__(128) char smem[];
    __shared__ int s_last;
    const uint32_t As_u = smem_u32(smem);
    const uint32_t Bs_u = As_u + 20480;

    const int tid  = threadIdx.x;
    const int lane = tid & 31, wid = tid >> 5;
    const int wm = wid & 3, wn = wid >> 2;
    const int g = lane >> 2, tig = lane & 3;
    const int mtile = blockIdx.x >> 2;
    const int q     = blockIdx.x & 3;
    const int ntbase = q * 8;

    auto prefetchB = [&](int ntg, int slot) {
        const __half* src = g_es + (size_t)ntg * BM * KU;       // slice h1 = e1
        const uint32_t dbase = Bs_u + slot * 16384;
#pragma unroll
        for (int i = 0; i < 4; i++) {
            int idx = tid + i * 256;
            int row = idx >> 3, c = idx & 7;
            cp16(dbase + row * 128 + ((c ^ (row & 7)) << 4),
                 src + (size_t)row * KU + c * 8);
        }
    };

    // ---- Prologue: A (fp32 x -> h1, swizzled), nh slice, B stages 0-2 -----
    {
        const float* xa = x + (size_t)mtile * BM * DIM;
#pragma unroll
        for (int i = 0; i < 4; i++) {
            int idx = tid + i * 256;
            int row = idx >> 3, c = idx & 7;
            const float* src = xa + (size_t)row * DIM + c * 8;
            float4 lo = __ldg(reinterpret_cast<const float4*>(src));
            float4 hi = __ldg(reinterpret_cast<const float4*>(src + 4));
            *reinterpret_cast<uint4*>(smem + row * 128 + ((c ^ (row & 7)) << 4)) =
                cvt8(lo, hi);
        }
        // nh slice: 1024 floats = 256 float4 (one per thread)
        *reinterpret_cast<float4*>(smem + 16384 + tid * 16) =
            __ldg(reinterpret_cast<const float4*>(g_nhn) + q * 256 + tid);
        prefetchB(ntbase + 0, 0); cp_commit();
        prefetchB(ntbase + 1, 1); cp_commit();
        prefetchB(ntbase + 2, 2); cp_commit();
    }

    const uint32_t amask = (lane & 7) << 4;
    const uint32_t asel  = lane >> 4;
    const uint32_t bmask = (lane & 7) << 4;
    const uint32_t bsel  = (lane >> 3) & 1;
    // ldsm4 B: lanes 0-15 -> ni, lanes 16-31 -> ni+1 (row +8)
    const uint32_t bRowOff = ((lane & 7) + ((lane >> 4) & 1) * 8) * 128;

    __syncthreads();   // A tile + nh visible

    // ---- Hoist A fragments: 2 mi x 4 ks, loaded ONCE ----------------------
    uint32_t ah[2][4][4];
#pragma unroll
    for (int mi = 0; mi < 2; mi++) {
        uint32_t aBase = As_u + (wm * 32 + mi * 16 + (lane & 15)) * 128;
#pragma unroll
        for (int ks = 0; ks < 4; ks++)
            ldsm4(ah[mi][ks], aBase + ((((uint32_t)(ks * 2) + asel) << 4) ^ amask));
    }

    uint32_t b1u[4], b2u[4];
#pragma unroll
    for (int s = 0; s < 4; s++) { b1u[s] = 0u; b2u[s] = 0u; }

    // ---- Mainloop: 8 nt stages, 2 col-halves each --------------------------
    for (int nt = 0; nt < 8; nt++) {
        CP_WAIT(2);
        __syncthreads();
        if (nt < 5) prefetchB(ntbase + nt + 3, (nt + 3) & 3);
        cp_commit();

        const uint32_t bst = Bs_u + (nt & 3) * 16384;
#pragma unroll
        for (int half = 0; half < 2; half++) {
            const int colb = nt * 128 + wn * 64 + half * 32 + tig * 2;  // local col
            const uint32_t bgrp = bst + (wn * 64 + half * 32) * 128 + bRowOff;
            float acc[2][4][4];
            {   // ks = 0: acc initialized with biased nh via C operand
                const uint32_t boff = (bsel << 4) ^ bmask;
#pragma unroll
                for (int nip = 0; nip < 2; nip++) {
                    uint32_t bb[4];
                    ldsm4(bb, bgrp + nip * 16 * 128 + boff);
                    const float2 nhA = *reinterpret_cast<const float2*>(
                        smem + 16384 + (colb + nip * 16) * 4);
                    const float2 nhB = *reinterpret_cast<const float2*>(
                        smem + 16384 + (colb + nip * 16 + 8) * 4);
                    hmma_c(acc[0][nip * 2],     ah[0][0], bb,     nhA.x, nhA.y);
                    hmma_c(acc[1][nip * 2],     ah[1][0], bb,     nhA.x, nhA.y);
                    hmma_c(acc[0][nip * 2 + 1], ah[0][0], bb + 2, nhB.x, nhB.y);
                    hmma_c(acc[1][nip * 2 + 1], ah[1][0], bb + 2, nhB.x, nhB.y);
                }
            }
#pragma unroll
            for (int ks = 1; ks < 4; ks++) {
                const uint32_t boff = (((uint32_t)(ks * 2) + bsel) << 4) ^ bmask;
#pragma unroll
                for (int nip = 0; nip < 2; nip++) {
                    uint32_t bb[4];
                    ldsm4(bb, bgrp + nip * 16 * 128 + boff);
                    hmma(acc[0][nip * 2],     ah[0][ks], bb);
                    hmma(acc[1][nip * 2],     ah[1][ks], bb);
                    hmma(acc[0][nip * 2 + 1], ah[0][ks], bb + 2);
                    hmma(acc[1][nip * 2 + 1], ah[1][ks], bb + 2);
                }
            }
            // ---- packed-key top-2 (7-bit ordinal) -------------------------
            const uint32_t obase = ((uint32_t)nt << 4) | ((uint32_t)half << 3);
#pragma unroll
            for (int ni = 0; ni < 4; ni++) {
                const uint32_t o0 = obase | ((uint32_t)ni << 1);
                const uint32_t o1 = o0 | 1u;
#pragma unroll
                for (int mi = 0; mi < 2; mi++) {
                    const int lo = mi * 2, hi = mi * 2 + 1;
                    uint32_t k0 = (__float_as_uint(acc[mi][ni][0]) & 0xFFFFFF80u) | o0;
                    uint32_t k1 = (__float_as_uint(acc[mi][ni][1]) & 0xFFFFFF80u) | o1;
                    uint32_t k2 = (__float_as_uint(acc[mi][ni][2]) & 0xFFFFFF80u) | o0;
                    uint32_t k3 = (__float_as_uint(acc[mi][ni][3]) & 0xFFFFFF80u) | o1;
                    b2u[lo] = umaxu(b2u[lo], uminu(b1u[lo], k0)); b1u[lo] = umaxu(b1u[lo], k0);
                    b2u[lo] = umaxu(b2u[lo], uminu(b1u[lo], k1)); b1u[lo] = umaxu(b1u[lo], k1);
                    b2u[hi] = umaxu(b2u[hi], uminu(b1u[hi], k2)); b1u[hi] = umaxu(b1u[hi], k2);
                    b2u[hi] = umaxu(b2u[hi], uminu(b1u[hi], k3)); b1u[hi] = umaxu(b1u[hi], k3);
                }
            }
        }
    }

    // ---- decode per-slot winners ------------------------------------------
    float b1[4], b2[4];
    int   i1[4];
#pragma unroll
    for (int s = 0; s < 4; s++) {
        uint32_t key = b1u[s];
        uint32_t ord = key & 127u;
        i1[s] = q * 1024 + (int)((ord >> 4) * 128 + wn * 64 + ((ord >> 3) & 1) * 32
                                 + ((ord >> 1) & 3) * 8 + tig * 2 + (ord & 1));
        b1[s] = __uint_as_float(key & 0xFFFFFF80u);
        b2[s] = __uint_as_float(b2u[s] & 0xFFFFFF80u);
    }

    // quad reduce (top-2 over disjoint candidate sets)
#pragma unroll
    for (int s = 0; s < 4; s++) {
#pragma unroll
        for (int d = 1; d < 4; d <<= 1) {
            float ov1 = __shfl_xor_sync(0xffffffffu, b1[s], d);
            int   oi1 = __shfl_xor_sync(0xffffffffu, i1[s], d);
            float ov2 = __shfl_xor_sync(0xffffffffu, b2[s], d);
            if (ov1 > b1[s] || (ov1 == b1[s] && oi1 < i1[s])) {
                b2[s] = fmaxf(b1[s], ov2); b1[s] = ov1; i1[s] = oi1;
            } else {
                b2[s] = fmaxf(b2[s], ov1);
            }
        }
    }
    __syncthreads();   // reuse smem (A region) for reduction
    float* rv1 = reinterpret_cast<float*>(smem);
    int*   ri1 = reinterpret_cast<int*>(smem + 1024);
    float* rv2 = reinterpret_cast<float*>(smem + 2048);
    if (tig == 0) {
#pragma unroll
        for (int s = 0; s < 4; s++) {
            int row = wm * 32 + (s >> 1) * 16 + (s & 1) * 8 + g;
            rv1[row * 2 + wn] = b1[s];
            ri1[row * 2 + wn] = i1[s];
            rv2[row * 2 + wn] = b2[s];
        }
    }
    __syncthreads();

    // per-row top-2 for this quarter -> global partials
    if (tid < BM) {
        float B1 = rv1[tid * 2], B2 = rv2[tid * 2];
        int   I1 = ri1[tid * 2];
        {
            float a1 = rv1[tid * 2 + 1], a2 = rv2[tid * 2 + 1];
            int   ai = ri1[tid * 2 + 1];
            if (a1 > B1 || (a1 == B1 && ai < I1)) {
                B2 = fmaxf(B1, a2); B1 = a1; I1 = ai;
            } else {
                B2 = fmaxf(B2, a1);
            }
        }
        const int pidx = (blockIdx.x) * BM + tid;   // (mtile*4+q)*128 + row
        g_pb1[pidx] = B1;
        g_pi1[pidx] = I1;
        g_pb2[pidx] = B2;
    }
    __threadfence();
    __syncthreads();
    if (tid == 0) {
        int r = atomicAdd(&g_qdone[mtile], 1);
        s_last = (r == 3) ? 1 : 0;
    }
    __syncthreads();

    // ---- last-of-4 merges the quarters, writes output, flags margins ------
    if (s_last && tid < BM) {
        __threadfence();
        const int base = mtile * 4 * BM + tid;
        float B1 = g_pb1[base], B2 = g_pb2[base];
        int   I1 = g_pi1[base];
#pragma unroll
        for (int qq = 1; qq < 4; qq++) {
            float a1 = g_pb1[base + qq * BM], a2 = g_pb2[base + qq * BM];
            int   ai = g_pi1[base + qq * BM];
            if (a1 > B1 || (a1 == B1 && ai < I1)) {
                B2 = fmaxf(B1, a2); B1 = a1; I1 = ai;
            } else {
                B2 = fmaxf(B2, a1);
            }
        }
        const int grow = mtile * BM + tid;
        if (out_ind) out_ind[grow] = (float)I1;
        const float4* e4 = reinterpret_cast<const float4*>(embed + (size_t)I1 * DIM);
        float4* o4 = reinterpret_cast<float4*>(outq + (size_t)grow * DIM);
#pragma unroll
        for (int i = 0; i < DIM / 4; i++) o4[i] = e4[i];
        if (B1 - B2 < TAU) {
            int pos = atomicAdd(&g_cnt, 1);
            if (pos < CAP) g_flag[pos] = grow;
        }
    }
}

// ---------------------------------------------------------------------------
// Rescore (exact 3-term) over flagged rows; A re-split from fp32 x inline.
// 8 codebook chunks x m-tiles; last-finishing chunk per tile writes back.
// ---------------------------------------------------------------------------
#define RS_SMEM (32768 + 65536)

template<int TERMS>
__device__ __forceinline__ void compute_stage(
    float (&acc)[4][4][4], const uint32_t* aBase, uint32_t amask, uint32_t asel,
    uint32_t bst, const uint32_t* bOff, uint32_t bmask, uint32_t bsel)
{
#pragma unroll
    for (int ks = 0; ks < 4; ks++) {
        uint32_t b[4][2];
        const uint32_t boff = (((uint32_t)(ks * 2) + bsel) << 4) ^ bmask;
#pragma unroll
        for (int ni = 0; ni < 4; ni++) ldsm2(b[ni], bst + bOff[ni] + boff);
        const uint32_t aoff = (((uint32_t)(ks * 2) + asel) << 4) ^ amask;
#pragma unroll
        for (int t = 0; t < TERMS; t++) {
            uint32_t a[4][4];
#pragma unroll
            for (int mi = 0; mi < 4; mi++)
                ldsm4(a[mi], aBase[mi] + t * 16384 + aoff);
#pragma unroll
            for (int mi = 0; mi < 4; mi++)
#pragma unroll
                for (int ni = 0; ni < 4; ni++)
                    hmma(acc[mi][ni], a[mi], b[ni]);
        }
    }
}

__global__ __launch_bounds__(256, 2)
void vq_rescore(const float* __restrict__ x,
                const float* __restrict__ embed,
                float* __restrict__ outq,
                float* __restrict__ out_ind) {
    int cnt = g_cnt; if (cnt > CAP) cnt = CAP;
    extern __shared__ __align__(128) char smem[];
    __shared__ int s_last;
    const uint32_t As_u = smem_u32(smem);
    const uint32_t Bs_u = As_u + 32768;

    const int tid  = threadIdx.x;
    const int lane = tid & 31, wid = tid >> 5;
    const int wm = wid & 1, wn = wid >> 1;
    const int g = lane >> 2, tig = lane & 3;
    const int nchunk = blockIdx.x;

    uint32_t aBase[4];
#pragma unroll
    for (int mi = 0; mi < 4; mi++)
        aBase[mi] = As_u + (wm * 64 + mi * 16 + (lane & 15)) * 128;
    const uint32_t amask = (lane & 7) << 4;
    const uint32_t asel  = lane >> 4;
    uint32_t bOff[4];
#pragma unroll
    for (int ni = 0; ni < 4; ni++)
        bOff[ni] = (wn * 32 + ni * 8 + (lane & 7)) * 128;
    const uint32_t bmask = (lane & 7) << 4;
    const uint32_t bsel  = (lane >> 3) & 1;

    auto prefetchB = [&](int st, int slot) {
        const int nt = nchunk * 4 + (st >> 1), s = st & 1;
        const __half* src = g_es + (size_t)nt * BM * KU + s * DIM;
        const uint32_t dbase = Bs_u + slot * 16384;
#pragma unroll
        for (int i = 0; i < 4; i++) {
            int idx = tid + i * 256;
            int row = idx >> 3, c = idx & 7;
            cp16(dbase + row * 128 + ((c ^ (row & 7)) << 4),
                 src + (size_t)row * KU + c * 8);
        }
    };

    for (int mt = blockIdx.y; mt * BM < cnt; mt += gridDim.y) {
#pragma unroll
        for (int i = 0; i < 4; i++) {
            int idx = tid + i * 256;
            int row = idx >> 3, c = idx & 7;
            int ci = mt * BM + row; if (ci >= cnt) ci = cnt - 1;
            int grow = g_flag[ci];
            const float* src = x + (size_t)grow * DIM + c * 8;
            float4 lo = __ldg(reinterpret_cast<const float4*>(src));
            float4 hi = __ldg(reinterpret_cast<const float4*>(src + 4));
            uint4 h[2];
            split8(lo, hi, h);
            uint32_t off = row * 128 + ((c ^ (row & 7)) << 4);
            *reinterpret_cast<uint4*>(smem + off)         = h[0];
            *reinterpret_cast<uint4*>(smem + 16384 + off) = h[1];
        }
        prefetchB(0, 0); cp_commit();
        prefetchB(1, 1); cp_commit();
        prefetchB(2, 2); cp_commit();

        float bestv[8]; int bidxv[8];
#pragma unroll
        for (int s = 0; s < 8; s++) { bestv[s] = -3.402823466e38f; bidxv[s] = 0; }
        float acc[4][4][4];

        for (int si = 0; si < 8; si++) {
            const int cs = si & 1, ntl = si >> 1;
            CP_WAIT(2);
            __syncthreads();
            if (si < 5) prefetchB(si + 3, (si + 3) & 3);
            cp_commit();

            if (cs == 0) {
#pragma unroll
                for (int mi = 0; mi < 4; mi++)
#pragma unroll
                    for (int ni = 0; ni < 4; ni++)
#pragma unroll
                        for (int r = 0; r < 4; r++) acc[mi][ni][r] = 0.f;
            }
            const uint32_t bst = Bs_u + (si & 3) * 16384;
            if (cs == 0) compute_stage<2>(acc, aBase, amask, asel, bst, bOff, bmask, bsel);
            else         compute_stage<1>(acc, aBase, amask, asel, bst, bOff, bmask, bsel);

            if (cs == 1) {
                const int colb = (nchunk * 4 + ntl) * 128 + wn * 32 + tig * 2;
#pragma unroll
                for (int ni = 0; ni < 4; ni++) {
                    const int c0 = colb + ni * 8;
                    float2 nh = *reinterpret_cast<const float2*>(&g_nhn[c0]);
#pragma unroll
                    for (int mi = 0; mi < 4; mi++) {
                        float s0 = acc[mi][ni][0] + nh.x;
                        float s1 = acc[mi][ni][1] + nh.y;
                        float s2 = acc[mi][ni][2] + nh.x;
                        float s3 = acc[mi][ni][3] + nh.y;
                        const int lo = mi * 2, hi = mi * 2 + 1;
                        if (s0 > bestv[lo]) { bestv[lo] = s0; bidxv[lo] = c0; }
                        if (s1 > bestv[lo]) { bestv[lo] = s1; bidxv[lo] = c0 + 1; }
                        if (s2 > bestv[hi]) { bestv[hi] = s2; bidxv[hi] = c0; }
                        if (s3 > bestv[hi]) { bestv[hi] = s3; bidxv[hi] = c0 + 1; }
                    }
                }
            }
        }

#pragma unroll
        for (int s = 0; s < 8; s++) {
#pragma unroll
            for (int d = 1; d < 4; d <<= 1) {
                float ov = __shfl_xor_sync(0xffffffffu, bestv[s], d);
                int   oi = __shfl_xor_sync(0xffffffffu, bidxv[s], d);
                if (ov > bestv[s] || (ov == bestv[s] && oi < bidxv[s])) {
                    bestv[s] = ov; bidxv[s] = oi;
                }
            }
        }
        __syncthreads();
        float* redv = reinterpret_cast<float*>(smem + 32768);
        int*   redi = reinterpret_cast<int*>(smem + 32768 + 2048);
        if (tig == 0) {
#pragma unroll
            for (int s = 0; s < 8; s++) {
                int row = wm * 64 + (s >> 1) * 16 + g + (s & 1) * 8;
                redv[row * 4 + wn] = bestv[s];
                redi[row * 4 + wn] = bidxv[s];
            }
        }
        __syncthreads();
        if (tid < BM && mt * BM + tid < cnt) {
            float bv = redv[tid * 4];
            int   bi = redi[tid * 4];
#pragma unroll
            for (int j = 1; j < 4; j++) {
                float v  = redv[tid * 4 + j];
                int   ii = redi[tid * 4 + j];
                if (v > bv || (v == bv && ii < bi)) { bv = v; bi = ii; }
            }
            unsigned long long packed =
                ((unsigned long long)fkey(bv) << 32) | (unsigned)(4095 - bi);
            atomicMax(&g_best[mt * BM + tid], packed);
        }
        __syncthreads();

        if (tid == 0) {
            __threadfence();
            int r = atomicAdd(&g_done[mt], 1);
            s_last = (r == 7) ? 1 : 0;
        }
        __syncthreads();
        if (s_last) {
            __threadfence();
            int li = mt * BM + (tid >> 1);
            if (li < cnt) {
                int row = g_flag[li];
                unsigned long long p = g_best[li];
                int idx = 4095 - (int)(p & 0xFFFu);
                int half = tid & 1;
                if (half == 0 && out_ind) out_ind[row] = (float)idx;
                const float4* e4 =
                    reinterpret_cast<const float4*>(embed + (size_t)idx * DIM) + half * 8;
                float4* o4 =
                    reinterpret_cast<float4*>(outq + (size_t)row * DIM) + half * 8;
#pragma unroll
                for (int j = 0; j < 8; j++) o4[j] = e4[j];
            }
        }
        __syncthreads();
    }
}

// Defensive tail fill (launched only when a tail exists).
__global__ void fill_kernel(float* __restrict__ out, int start, int end) {
    int i = start + blockIdx.x * blockDim.x + threadIdx.x;
    if (i < end) out[i] = 0.f;
}

// ---------------------------------------------------------------------------
extern "C" void kernel_launch(void* const* d_in, const int* in_sizes, int n_in,
                              void* d_out, int out_size) {
    const float* x     = (const float*)d_in[0];
    const float* embed = (const float*)d_in[1];
    float* out = (float*)d_out;

    const int M = in_sizes[0] / DIM;  // 32768

    prep_kernel<<<128, 256>>>(embed);

    cudaFuncSetAttribute(vq_pass1,
                         cudaFuncAttributeMaxDynamicSharedMemorySize, P1_SMEM);
    cudaFuncSetAttribute(vq_rescore,
                         cudaFuncAttributeMaxDynamicSharedMemorySize, RS_SMEM);

    float* oind = (out_size >= M * DIM + M) ? (out + (size_t)M * DIM) : nullptr;
    vq_pass1<<<(M / BM) * 4, 256, P1_SMEM>>>(x, embed, out, oind);
    vq_rescore<<<dim3(8, 16), 256, RS_SMEM>>>(x, embed, out, oind);

    int written = M * DIM + (oind ? M : 0);
    if (out_size > written) {
        int tail = out_size - written;
        fill_kernel<<<(tail + 255) / 256, 256>>>(out, written, out_size);
    }
}